// round 1
// baseline (speedup 1.0000x reference)
#include <cuda_runtime.h>
#include <math.h>

#define DIM   128
#define NH    4
#define HD    32
#define WS    7
#define SS    3
#define ZP    14
#define HP    56
#define WP    56
#define NTOK  343
#define NWIN  256
#define NROWS (NWIN * NTOK)   // 87808
#define NMLP  512

// -------- scratch (static device globals; allocation-free) --------
__device__ float g_xw [NROWS * DIM];        // LN1'd, shifted, windowed
__device__ float g_qkv[NROWS * 3 * DIM];    // qkv per window-row
__device__ float g_att[NROWS * DIM];        // attention output (window layout)
__device__ float g_x1 [NROWS * DIM];        // residual-1 (natural layout)
__device__ float g_xn2[NROWS * DIM];        // LN2 output
__device__ float g_h  [NROWS * NMLP];       // MLP hidden

// window row -> natural row (shift-back + window-reverse), also used as gather source for LN1
__device__ __forceinline__ int nat_row(int r) {
    int w = r / NTOK, t = r - w * NTOK;
    int b = w >> 7, wi = w & 127;
    int wz = wi >> 6, wy = (wi >> 3) & 7, wx = wi & 7;
    int lz = t / 49, rem = t - lz * 49, ly = rem / 7, lx = rem - ly * 7;
    int z = wz * WS + lz + SS; if (z >= ZP) z -= ZP;
    int y = wy * WS + ly + SS; if (y >= HP) y -= HP;
    int x = wx * WS + lx + SS; if (x >= WP) x -= WP;
    return ((b * ZP + z) * HP + y) * WP + x;
}

__device__ __forceinline__ int region3(int g, int P) {
    return (g < P - WS) ? 0 : ((g < P - SS) ? 1 : 2);
}

// -------- LayerNorm (one warp per token; optional gather through nat_row) --------
__global__ void ln_kernel(const float* __restrict__ src, const float* __restrict__ g,
                          const float* __restrict__ b, float* __restrict__ dst, int gather) {
    int token = blockIdx.x * 8 + (threadIdx.x >> 5);
    int lane  = threadIdx.x & 31;
    int srow  = gather ? nat_row(token) : token;
    float4 v = ((const float4*)(src + (size_t)srow * DIM))[lane];
    float s  = v.x + v.y + v.z + v.w;
    float ss = v.x * v.x + v.y * v.y + v.z * v.z + v.w * v.w;
#pragma unroll
    for (int o = 16; o; o >>= 1) {
        s  += __shfl_xor_sync(0xffffffffu, s,  o);
        ss += __shfl_xor_sync(0xffffffffu, ss, o);
    }
    float mean = s * (1.f / 128.f);
    float var  = ss * (1.f / 128.f) - mean * mean;
    float inv  = rsqrtf(var + 1e-5f);
    float4 gg = ((const float4*)g)[lane];
    float4 bb = ((const float4*)b)[lane];
    float4 o;
    o.x = (v.x - mean) * inv * gg.x + bb.x;
    o.y = (v.y - mean) * inv * gg.y + bb.y;
    o.z = (v.z - mean) * inv * gg.z + bb.z;
    o.w = (v.w - mean) * inv * gg.w + bb.w;
    ((float4*)(dst + (size_t)token * DIM))[lane] = o;
}

// -------- Tiled SGEMM: C[M,N] = A[M,K] @ B[K,N] (+ epilogues) --------
// BM=128, BN=64, BK=16, 256 threads, 8x4 per-thread microtile.
// EPI 0: +bias            (qkv)
// EPI 1: +bias, GELU      (fc1)
// EPI 2: +bias, scatter to nat_row, + residual res[nat]   (proj + residual-1)
// EPI 3: +bias, + residual res[r]                          (fc2 + residual-2)
template <int EPI>
__global__ void __launch_bounds__(256) gemm_kernel(
        const float* __restrict__ A, const float* __restrict__ B,
        const float* __restrict__ bias, const float* __restrict__ res,
        float* __restrict__ C, int M, int N, int K) {
    __shared__ float As[16][128];
    __shared__ float Bs[16][68];

    const int tid = threadIdx.x;
    const int bm = blockIdx.y * 128, bn = blockIdx.x * 64;
    const int tx = tid & 15, ty = tid >> 4;

    const int arow  = tid >> 2;
    const int acol4 = (tid & 3) * 4;
    const int brow  = tid >> 4;
    const int bcol4 = (tid & 15) * 4;

    float acc[8][4];
#pragma unroll
    for (int i = 0; i < 8; i++)
#pragma unroll
        for (int j = 0; j < 4; j++) acc[i][j] = 0.f;

    for (int k0 = 0; k0 < K; k0 += 16) {
        float4 a0 = *(const float4*)(A + (size_t)(bm + arow) * K + k0 + acol4);
        float4 a1 = *(const float4*)(A + (size_t)(bm + arow + 64) * K + k0 + acol4);
        float4 b0 = *(const float4*)(B + (size_t)(k0 + brow) * N + bn + bcol4);
        As[acol4 + 0][arow] = a0.x; As[acol4 + 1][arow] = a0.y;
        As[acol4 + 2][arow] = a0.z; As[acol4 + 3][arow] = a0.w;
        As[acol4 + 0][arow + 64] = a1.x; As[acol4 + 1][arow + 64] = a1.y;
        As[acol4 + 2][arow + 64] = a1.z; As[acol4 + 3][arow + 64] = a1.w;
        *(float4*)&Bs[brow][bcol4] = b0;
        __syncthreads();
#pragma unroll
        for (int k = 0; k < 16; k++) {
            float4 ta0 = *(float4*)&As[k][ty * 8];
            float4 ta1 = *(float4*)&As[k][ty * 8 + 4];
            float4 tb  = *(float4*)&Bs[k][tx * 4];
            float av[8] = {ta0.x, ta0.y, ta0.z, ta0.w, ta1.x, ta1.y, ta1.z, ta1.w};
            float bv[4] = {tb.x, tb.y, tb.z, tb.w};
#pragma unroll
            for (int i = 0; i < 8; i++)
#pragma unroll
                for (int j = 0; j < 4; j++) acc[i][j] += av[i] * bv[j];
        }
        __syncthreads();
    }

#pragma unroll
    for (int i = 0; i < 8; i++) {
        int r = bm + ty * 8 + i;
        int outr = (EPI == 2) ? nat_row(r) : r;
#pragma unroll
        for (int j = 0; j < 4; j++) {
            int c = bn + tx * 4 + j;
            float v = acc[i][j] + bias[c];
            if (EPI == 1) v = 0.5f * v * (1.f + erff(v * 0.7071067811865475f));
            if (EPI == 2) v += res[(size_t)outr * DIM + c];
            if (EPI == 3) v += res[(size_t)r * DIM + c];
            C[(size_t)outr * N + c] = v;
        }
    }
}

// -------- Fused window attention: one CTA per (window, head) --------
// smem: q,k,v [343][33] + 32 prob rows [343]  -> 179,732 B dynamic
#define ATTN_SMEM ((3 * NTOK * 33 + 32 * NTOK) * 4)

__global__ void __launch_bounds__(512, 1) attn_kernel(
        const float* __restrict__ qkv, const float* __restrict__ rel,
        float* __restrict__ attout) {
    extern __shared__ float sm[];
    float* sq = sm;
    float* sk = sm + NTOK * 33;
    float* sv = sm + 2 * NTOK * 33;
    float* sp = sm + 3 * NTOK * 33;

    const int w = blockIdx.x >> 2;
    const int h = blockIdx.x & 3;
    const int tid = threadIdx.x;
    const int lane = tid & 31;
    const int warp = tid >> 5;

    // stage q (pre-scaled), k, v
    for (int idx = tid; idx < NTOK * HD; idx += 512) {
        int t = idx >> 5, d = idx & 31;
        const float* base = qkv + (size_t)(w * NTOK + t) * (3 * DIM) + h * HD + d;
        sq[t * 33 + d] = base[0] * 0.17677669529663687f;  // 1/sqrt(32)
        sk[t * 33 + d] = base[DIM];
        sv[t * 33 + d] = base[2 * DIM];
    }
    __syncthreads();

    const int wi  = w & 127;
    const int gz0 = (wi >> 6) * WS, gy0 = ((wi >> 3) & 7) * WS, gx0 = (wi & 7) * WS;

    // per-lane key metadata: packed (mz*169+my*13+mx) | region<<20, for m = lane+32*t
    int mcode[11];
#pragma unroll
    for (int tI = 0; tI < 11; tI++) {
        int m = lane + 32 * tI;
        if (m < NTOK) {
            int mz = m / 49, r2 = m - mz * 49, my = r2 / 7, mx = r2 - my * 7;
            int reg = region3(gz0 + mz, ZP) * 9 + region3(gy0 + my, HP) * 3 + region3(gx0 + mx, WP);
            mcode[tI] = (mz * 169 + my * 13 + mx) | (reg << 20);
        } else mcode[tI] = 0;
    }
    const int CBASE = 6 * 169 + 6 * 13 + 6;

    for (int i0 = warp * 2; i0 < NTOK; i0 += 32) {
        const int i1 = i0 + 1;
        const bool has1 = (i1 < NTOK);
        float qr0[32], qr1[32];
#pragma unroll
        for (int d = 0; d < 32; d++) {
            qr0[d] = sq[i0 * 33 + d];
            qr1[d] = has1 ? sq[i1 * 33 + d] : 0.f;
        }
        int iz0 = i0 / 49, r0_ = i0 - iz0 * 49, iy0 = r0_ / 7, ix0 = r0_ - iy0 * 7;
        int ci0 = iz0 * 169 + iy0 * 13 + ix0 + CBASE;
        int ireg0 = region3(gz0 + iz0, ZP) * 9 + region3(gy0 + iy0, HP) * 3 + region3(gx0 + ix0, WP);
        int i1c = has1 ? i1 : 0;
        int iz1 = i1c / 49, r1_ = i1c - iz1 * 49, iy1 = r1_ / 7, ix1 = r1_ - iy1 * 7;
        int ci1 = iz1 * 169 + iy1 * 13 + ix1 + CBASE;
        int ireg1 = region3(gz0 + iz1, ZP) * 9 + region3(gy0 + iy1, HP) * 3 + region3(gx0 + ix1, WP);

        float s0[11], s1[11];
        float mx0 = -1e30f, mx1 = -1e30f;
#pragma unroll
        for (int tI = 0; tI < 11; tI++) {
            int m = lane + 32 * tI;
            if (m < NTOK) {
                float a0 = 0.f, a1 = 0.f;
#pragma unroll
                for (int d = 0; d < 32; d++) {
                    float kv = sk[m * 33 + d];
                    a0 += qr0[d] * kv;
                    a1 += qr1[d] * kv;
                }
                int mc   = mcode[tI] & 0xFFFFF;
                int mreg = mcode[tI] >> 20;
                a0 += rel[(ci0 - mc) * NH + h];
                a1 += rel[(ci1 - mc) * NH + h];
                if (ireg0 != mreg) a0 -= 100.f;
                if (ireg1 != mreg) a1 -= 100.f;
                s0[tI] = a0; s1[tI] = a1;
                mx0 = fmaxf(mx0, a0); mx1 = fmaxf(mx1, a1);
            }
        }
#pragma unroll
        for (int o = 16; o; o >>= 1) {
            mx0 = fmaxf(mx0, __shfl_xor_sync(0xffffffffu, mx0, o));
            mx1 = fmaxf(mx1, __shfl_xor_sync(0xffffffffu, mx1, o));
        }
        float sum0 = 0.f, sum1 = 0.f;
#pragma unroll
        for (int tI = 0; tI < 11; tI++) {
            int m = lane + 32 * tI;
            if (m < NTOK) {
                s0[tI] = __expf(s0[tI] - mx0); sum0 += s0[tI];
                s1[tI] = __expf(s1[tI] - mx1); sum1 += s1[tI];
            }
        }
#pragma unroll
        for (int o = 16; o; o >>= 1) {
            sum0 += __shfl_xor_sync(0xffffffffu, sum0, o);
            sum1 += __shfl_xor_sync(0xffffffffu, sum1, o);
        }
        float inv0 = 1.f / sum0, inv1 = 1.f / sum1;
        float* p0 = sp + (warp * 2) * NTOK;
        float* p1 = p0 + NTOK;
#pragma unroll
        for (int tI = 0; tI < 11; tI++) {
            int m = lane + 32 * tI;
            if (m < NTOK) { p0[m] = s0[tI] * inv0; p1[m] = s1[tI] * inv1; }
        }
        __syncwarp();
        float acc0 = 0.f, acc1 = 0.f;
#pragma unroll 7
        for (int m = 0; m < NTOK; m++) {
            float vv = sv[m * 33 + lane];
            acc0 += p0[m] * vv;
            acc1 += p1[m] * vv;
        }
        size_t ob = ((size_t)w * NTOK + i0) * DIM + h * HD + lane;
        attout[ob] = acc0;
        if (has1) attout[ob + DIM] = acc1;
        __syncwarp();
    }
}

// -------- launch --------
extern "C" void kernel_launch(void* const* d_in, const int* in_sizes, int n_in,
                              void* d_out, int out_size) {
    const float* x     = (const float*)d_in[0];
    const float* n1g   = (const float*)d_in[1];
    const float* n1b   = (const float*)d_in[2];
    const float* qkvw  = (const float*)d_in[3];
    const float* qkvb  = (const float*)d_in[4];
    const float* rel   = (const float*)d_in[5];
    const float* projw = (const float*)d_in[6];
    const float* projb = (const float*)d_in[7];
    const float* n2g   = (const float*)d_in[8];
    const float* n2b   = (const float*)d_in[9];
    const float* fc1w  = (const float*)d_in[10];
    const float* fc1b  = (const float*)d_in[11];
    const float* fc2w  = (const float*)d_in[12];
    const float* fc2b  = (const float*)d_in[13];
    float* out = (float*)d_out;

    float *xw, *qkvp, *att, *x1, *xn2, *hbuf;
    cudaGetSymbolAddress((void**)&xw,   g_xw);
    cudaGetSymbolAddress((void**)&qkvp, g_qkv);
    cudaGetSymbolAddress((void**)&att,  g_att);
    cudaGetSymbolAddress((void**)&x1,   g_x1);
    cudaGetSymbolAddress((void**)&xn2,  g_xn2);
    cudaGetSymbolAddress((void**)&hbuf, g_h);

    cudaFuncSetAttribute(attn_kernel, cudaFuncAttributeMaxDynamicSharedMemorySize, ATTN_SMEM);

    // 1) LN1 + shift + window partition
    ln_kernel<<<NROWS / 8, 256>>>(x, n1g, n1b, xw, 1);
    // 2) QKV GEMM
    gemm_kernel<0><<<dim3(384 / 64, NROWS / 128), 256>>>(xw, qkvw, qkvb, nullptr, qkvp, NROWS, 384, 128);
    // 3) windowed attention (bias + mask + softmax + PV)
    attn_kernel<<<NWIN * NH, 512, ATTN_SMEM>>>(qkvp, rel, att);
    // 4) proj GEMM + window-reverse + unshift + residual
    gemm_kernel<2><<<dim3(128 / 64, NROWS / 128), 256>>>(att, projw, projb, x, x1, NROWS, 128, 128);
    // 5) LN2
    ln_kernel<<<NROWS / 8, 256>>>(x1, n2g, n2b, xn2, 0);
    // 6) fc1 + GELU
    gemm_kernel<1><<<dim3(512 / 64, NROWS / 128), 256>>>(xn2, fc1w, fc1b, nullptr, hbuf, NROWS, 512, 128);
    // 7) fc2 + residual -> output
    gemm_kernel<3><<<dim3(128 / 64, NROWS / 128), 256>>>(hbuf, fc2w, fc2b, x1, out, NROWS, 128, 512);
}

// round 2
// speedup vs baseline: 1.7918x; 1.7918x over previous
#include <cuda_runtime.h>
#include <cuda_fp16.h>
#include <math.h>

#define DIM   128
#define NH    4
#define HD    32
#define WS    7
#define SS    3
#define ZP    14
#define HP    56
#define WP    56
#define NTOK  343
#define NWIN  256
#define NROWS (NWIN * NTOK)   // 87808
#define NMLP  512

// -------- scratch (static device globals; allocation-free) --------
__device__ float  g_xw [NROWS * DIM];        // LN1'd, shifted, windowed
__device__ float  g_qkv[NROWS * 3 * DIM];    // qkv per window-row
__device__ float  g_att[NROWS * DIM];        // attention output (window layout)
__device__ float  g_x1 [NROWS * DIM];        // residual-1 (natural layout)
__device__ float  g_xn2[NROWS * DIM];        // LN2 output
__device__ __half g_h  [NROWS * NMLP];       // MLP hidden (fp16)

// window row -> natural row (shift-back + window-reverse)
__device__ __forceinline__ int nat_row(int r) {
    int w = r / NTOK, t = r - w * NTOK;
    int b = w >> 7, wi = w & 127;
    int wz = wi >> 6, wy = (wi >> 3) & 7, wx = wi & 7;
    int lz = t / 49, rem = t - lz * 49, ly = rem / 7, lx = rem - ly * 7;
    int z = wz * WS + lz + SS; if (z >= ZP) z -= ZP;
    int y = wy * WS + ly + SS; if (y >= HP) y -= HP;
    int x = wx * WS + lx + SS; if (x >= WP) x -= WP;
    return ((b * ZP + z) * HP + y) * WP + x;
}

__device__ __forceinline__ int region3(int g, int P) {
    return (g < P - WS) ? 0 : ((g < P - SS) ? 1 : 2);
}

// -------- LayerNorm (one warp per token; optional gather through nat_row) --------
__global__ void ln_kernel(const float* __restrict__ src, const float* __restrict__ g,
                          const float* __restrict__ b, float* __restrict__ dst, int gather) {
    int token = blockIdx.x * 8 + (threadIdx.x >> 5);
    int lane  = threadIdx.x & 31;
    int srow  = gather ? nat_row(token) : token;
    float4 v = ((const float4*)(src + (size_t)srow * DIM))[lane];
    float s  = v.x + v.y + v.z + v.w;
    float ss = v.x * v.x + v.y * v.y + v.z * v.z + v.w * v.w;
#pragma unroll
    for (int o = 16; o; o >>= 1) {
        s  += __shfl_xor_sync(0xffffffffu, s,  o);
        ss += __shfl_xor_sync(0xffffffffu, ss, o);
    }
    float mean = s * (1.f / 128.f);
    float var  = ss * (1.f / 128.f) - mean * mean;
    float inv  = rsqrtf(var + 1e-5f);
    float4 gg = ((const float4*)g)[lane];
    float4 bb = ((const float4*)b)[lane];
    float4 o;
    o.x = (v.x - mean) * inv * gg.x + bb.x;
    o.y = (v.y - mean) * inv * gg.y + bb.y;
    o.z = (v.z - mean) * inv * gg.z + bb.z;
    o.w = (v.w - mean) * inv * gg.w + bb.w;
    ((float4*)(dst + (size_t)token * DIM))[lane] = o;
}

// ================= tensor-core GEMM (mma.sync m16n8k16, f16 in / f32 acc) ==========
// BM=128, BN=128, BK=32, 256 threads = 8 warps in 2(m) x 4(n), warp tile 64x32.
// EPI 0: +bias                       (qkv)
// EPI 1: +bias, GELU, write half     (fc1)
// EPI 2: +bias, scatter nat_row, +res[nat]  (proj + residual-1)
// EPI 3: +bias, +res[r]              (fc2 + residual-2)
#define BM 128
#define BN 128
#define BK 32

struct __align__(16) GemmSmem {
    __half A[2][BM][40];    // pitch 40 halfs (80B) -> conflict-free ldmatrix
    __half B[2][BK][136];   // pitch 136 halfs (272B) -> conflict-free ldmatrix.trans
};

__device__ __forceinline__ void ldsm_x4(unsigned (&r)[4], unsigned addr) {
    asm volatile("ldmatrix.sync.aligned.m8n8.x4.shared.b16 {%0,%1,%2,%3}, [%4];"
                 : "=r"(r[0]), "=r"(r[1]), "=r"(r[2]), "=r"(r[3]) : "r"(addr));
}
__device__ __forceinline__ void ldsm_x4_t(unsigned (&r)[4], unsigned addr) {
    asm volatile("ldmatrix.sync.aligned.m8n8.x4.trans.shared.b16 {%0,%1,%2,%3}, [%4];"
                 : "=r"(r[0]), "=r"(r[1]), "=r"(r[2]), "=r"(r[3]) : "r"(addr));
}
__device__ __forceinline__ void mma16816(float (&c)[4], const unsigned (&a)[4],
                                         unsigned b0, unsigned b1) {
    asm volatile("mma.sync.aligned.m16n8k16.row.col.f32.f16.f16.f32 "
                 "{%0,%1,%2,%3},{%4,%5,%6,%7},{%8,%9},{%0,%1,%2,%3};"
                 : "+f"(c[0]), "+f"(c[1]), "+f"(c[2]), "+f"(c[3])
                 : "r"(a[0]), "r"(a[1]), "r"(a[2]), "r"(a[3]), "r"(b0), "r"(b1));
}

template <int EPI, typename AT, typename CT>
__global__ void __launch_bounds__(256) mma_gemm(
        const AT* __restrict__ A, const float* __restrict__ B,
        const float* __restrict__ bias, const float* __restrict__ res,
        CT* __restrict__ C, int M, int N, int K) {
    __shared__ GemmSmem sm;
    constexpr bool HALF_A = (sizeof(AT) == 2);

    const int tid  = threadIdx.x;
    const int lane = tid & 31, warp = tid >> 5;
    const int mw = warp >> 2, nw = warp & 3;           // 2 x 4 warp grid
    const int bm = blockIdx.y * BM, bn = blockIdx.x * BN;

    // staging assignments
    const int arow = tid >> 1;
    const int brow = tid >> 3;
    const int bcol0 = (tid & 7) * 4;

    float acc[4][4][4];
#pragma unroll
    for (int i = 0; i < 4; i++)
#pragma unroll
        for (int j = 0; j < 4; j++)
#pragma unroll
            for (int l = 0; l < 4; l++) acc[i][j][l] = 0.f;

    float4 afr[4]; uint4 ahr[2]; float4 bfr[4];

    auto loadT = [&](int it) {
        int k0 = it * BK;
        if constexpr (HALF_A) {
            const __half* p = A + (size_t)(bm + arow) * K + k0 + (tid & 1) * 16;
            ahr[0] = *(const uint4*)p;
            ahr[1] = *(const uint4*)(p + 8);
        } else {
            const float* p = (const float*)A + (size_t)(bm + arow) * K + k0 + (tid & 1) * 16;
#pragma unroll
            for (int j = 0; j < 4; j++) afr[j] = *(const float4*)(p + j * 4);
        }
        const float* q = B + (size_t)(k0 + brow) * N + bn + bcol0;
#pragma unroll
        for (int j = 0; j < 4; j++) bfr[j] = *(const float4*)(q + j * 32);
    };
    auto stsT = [&](int buf) {
        if constexpr (HALF_A) {
            int pc = (tid & 1) * 16;
            *(uint4*)&sm.A[buf][arow][pc]     = ahr[0];
            *(uint4*)&sm.A[buf][arow][pc + 8] = ahr[1];
        } else {
            int pc = (tid & 1) * 16;
#pragma unroll
            for (int j = 0; j < 4; j++) {
                __half2 h01 = __floats2half2_rn(afr[j].x, afr[j].y);
                __half2 h23 = __floats2half2_rn(afr[j].z, afr[j].w);
                *(__half2*)&sm.A[buf][arow][pc + j * 4]     = h01;
                *(__half2*)&sm.A[buf][arow][pc + j * 4 + 2] = h23;
            }
        }
#pragma unroll
        for (int j = 0; j < 4; j++) {
            __half2 h01 = __floats2half2_rn(bfr[j].x, bfr[j].y);
            __half2 h23 = __floats2half2_rn(bfr[j].z, bfr[j].w);
            *(__half2*)&sm.B[buf][brow][bcol0 + j * 32]     = h01;
            *(__half2*)&sm.B[buf][brow][bcol0 + j * 32 + 2] = h23;
        }
    };

    const unsigned aLane = ((lane & 15) * 40 + (lane >> 4) * 8) * 2;
    const unsigned bLane = (((lane & 7) + ((lane >> 3) & 1) * 8) * 136 + (lane >> 4) * 8) * 2;

    const int niter = K / BK;
    loadT(0);
    stsT(0);
    for (int it = 0; it < niter; it++) {
        __syncthreads();
        bool more = (it + 1 < niter);
        if (more) loadT(it + 1);
        int buf = it & 1;
        unsigned aBase = (unsigned)__cvta_generic_to_shared(&sm.A[buf][0][0])
                         + aLane + (unsigned)(mw * 64 * 40 * 2);
        unsigned bBase = (unsigned)__cvta_generic_to_shared(&sm.B[buf][0][0])
                         + bLane + (unsigned)(nw * 32 * 2);
#pragma unroll
        for (int ks = 0; ks < 2; ks++) {
            unsigned a[4][4], b[2][4];
#pragma unroll
            for (int mf = 0; mf < 4; mf++)
                ldsm_x4(a[mf], aBase + mf * (16 * 40 * 2) + ks * 32);
#pragma unroll
            for (int np = 0; np < 2; np++)
                ldsm_x4_t(b[np], bBase + np * 32 + ks * (16 * 136 * 2));
#pragma unroll
            for (int mf = 0; mf < 4; mf++)
#pragma unroll
                for (int nf = 0; nf < 4; nf++)
                    mma16816(acc[mf][nf], a[mf], b[nf >> 1][(nf & 1) * 2],
                             b[nf >> 1][(nf & 1) * 2 + 1]);
        }
        if (more) stsT((it + 1) & 1);
    }

    // epilogue
#pragma unroll
    for (int mf = 0; mf < 4; mf++) {
        int r0 = bm + mw * 64 + mf * 16 + (lane >> 2);
        int r1 = r0 + 8;
        int or0 = (EPI == 2) ? nat_row(r0) : r0;
        int or1 = (EPI == 2) ? nat_row(r1) : r1;
#pragma unroll
        for (int nf = 0; nf < 4; nf++) {
            int c = bn + nw * 32 + nf * 8 + (lane & 3) * 2;
            float bv0 = bias[c], bv1 = bias[c + 1];
            float v00 = acc[mf][nf][0] + bv0, v01 = acc[mf][nf][1] + bv1;
            float v10 = acc[mf][nf][2] + bv0, v11 = acc[mf][nf][3] + bv1;
            if (EPI == 1) {
                v00 = 0.5f * v00 * (1.f + erff(v00 * 0.7071067811865475f));
                v01 = 0.5f * v01 * (1.f + erff(v01 * 0.7071067811865475f));
                v10 = 0.5f * v10 * (1.f + erff(v10 * 0.7071067811865475f));
                v11 = 0.5f * v11 * (1.f + erff(v11 * 0.7071067811865475f));
            }
            if (EPI == 2) {
                v00 += res[(size_t)or0 * DIM + c];   v01 += res[(size_t)or0 * DIM + c + 1];
                v10 += res[(size_t)or1 * DIM + c];   v11 += res[(size_t)or1 * DIM + c + 1];
            }
            if (EPI == 3) {
                v00 += res[(size_t)r0 * DIM + c];    v01 += res[(size_t)r0 * DIM + c + 1];
                v10 += res[(size_t)r1 * DIM + c];    v11 += res[(size_t)r1 * DIM + c + 1];
            }
            if constexpr (sizeof(CT) == 2) {
                *(__half2*)((__half*)C + (size_t)or0 * N + c) = __floats2half2_rn(v00, v01);
                *(__half2*)((__half*)C + (size_t)or1 * N + c) = __floats2half2_rn(v10, v11);
            } else {
                *(float2*)((float*)C + (size_t)or0 * N + c) = make_float2(v00, v01);
                *(float2*)((float*)C + (size_t)or1 * N + c) = make_float2(v10, v11);
            }
        }
    }
}

// -------- Fused window attention: one CTA per (window, head) --------
// smem: q,k,v [343][36] + 16 warp prob pair-rows [343][2] -> 192,080 B dynamic
#define ATTN_SMEM ((3 * NTOK * 36 + 16 * NTOK * 2) * 4)

__global__ void __launch_bounds__(512, 1) attn_kernel(
        const float* __restrict__ qkv, const float* __restrict__ rel,
        float* __restrict__ attout) {
    extern __shared__ float smf[];
    float* sq = smf;
    float* sk = smf + NTOK * 36;
    float* sv = smf + 2 * NTOK * 36;
    float* sp = smf + 3 * NTOK * 36;

    const int w = blockIdx.x >> 2;
    const int h = blockIdx.x & 3;
    const int tid = threadIdx.x;
    const int lane = tid & 31;
    const int warp = tid >> 5;

    // stage q (pre-scaled), k, v  (vectorized)
    for (int idx = tid; idx < NTOK * 8; idx += 512) {
        int t = idx >> 3, d4 = (idx & 7) * 4;
        const float* base = qkv + (size_t)(w * NTOK + t) * (3 * DIM) + h * HD + d4;
        float4 qv = *(const float4*)base;
        float4 kv = *(const float4*)(base + DIM);
        float4 vv = *(const float4*)(base + 2 * DIM);
        qv.x *= 0.17677669529663687f; qv.y *= 0.17677669529663687f;
        qv.z *= 0.17677669529663687f; qv.w *= 0.17677669529663687f;
        *(float4*)&sq[t * 36 + d4] = qv;
        *(float4*)&sk[t * 36 + d4] = kv;
        *(float4*)&sv[t * 36 + d4] = vv;
    }
    __syncthreads();

    const int wi  = w & 127;
    const int gz0 = (wi >> 6) * WS, gy0 = ((wi >> 3) & 7) * WS, gx0 = (wi & 7) * WS;

    int mcode[11];
#pragma unroll
    for (int tI = 0; tI < 11; tI++) {
        int m = lane + 32 * tI;
        if (m < NTOK) {
            int mz = m / 49, r2 = m - mz * 49, my = r2 / 7, mx = r2 - my * 7;
            int reg = region3(gz0 + mz, ZP) * 9 + region3(gy0 + my, HP) * 3 + region3(gx0 + mx, WP);
            mcode[tI] = (mz * 169 + my * 13 + mx) | (reg << 20);
        } else mcode[tI] = 0;
    }
    const int CBASE = 6 * 169 + 6 * 13 + 6;
    float* spw = sp + warp * (NTOK * 2);

    for (int i0 = warp * 2; i0 < NTOK; i0 += 32) {
        const int i1 = i0 + 1;
        const bool has1 = (i1 < NTOK);
        float qr0[32], qr1[32];
#pragma unroll
        for (int d4 = 0; d4 < 32; d4 += 4) {
            float4 q0 = *(const float4*)&sq[i0 * 36 + d4];
            qr0[d4] = q0.x; qr0[d4 + 1] = q0.y; qr0[d4 + 2] = q0.z; qr0[d4 + 3] = q0.w;
            float4 q1 = has1 ? *(const float4*)&sq[i1 * 36 + d4] : make_float4(0, 0, 0, 0);
            qr1[d4] = q1.x; qr1[d4 + 1] = q1.y; qr1[d4 + 2] = q1.z; qr1[d4 + 3] = q1.w;
        }
        int iz0 = i0 / 49, r0_ = i0 - iz0 * 49, iy0 = r0_ / 7, ix0 = r0_ - iy0 * 7;
        int ci0 = iz0 * 169 + iy0 * 13 + ix0 + CBASE;
        int ireg0 = region3(gz0 + iz0, ZP) * 9 + region3(gy0 + iy0, HP) * 3 + region3(gx0 + ix0, WP);
        int i1c = has1 ? i1 : 0;
        int iz1 = i1c / 49, r1_ = i1c - iz1 * 49, iy1 = r1_ / 7, ix1 = r1_ - iy1 * 7;
        int ci1 = iz1 * 169 + iy1 * 13 + ix1 + CBASE;
        int ireg1 = region3(gz0 + iz1, ZP) * 9 + region3(gy0 + iy1, HP) * 3 + region3(gx0 + ix1, WP);

        float s0[11], s1[11];
        float mx0 = -1e30f, mx1 = -1e30f;
#pragma unroll
        for (int tI = 0; tI < 11; tI++) {
            int m = lane + 32 * tI;
            if (m < NTOK) {
                float a0 = 0.f, a1 = 0.f;
#pragma unroll
                for (int d4 = 0; d4 < 32; d4 += 4) {
                    float4 kv = *(const float4*)&sk[m * 36 + d4];
                    a0 += qr0[d4] * kv.x + qr0[d4 + 1] * kv.y + qr0[d4 + 2] * kv.z + qr0[d4 + 3] * kv.w;
                    a1 += qr1[d4] * kv.x + qr1[d4 + 1] * kv.y + qr1[d4 + 2] * kv.z + qr1[d4 + 3] * kv.w;
                }
                int mc   = mcode[tI] & 0xFFFFF;
                int mreg = mcode[tI] >> 20;
                a0 += rel[(ci0 - mc) * NH + h];
                a1 += rel[(ci1 - mc) * NH + h];
                if (ireg0 != mreg) a0 -= 100.f;
                if (ireg1 != mreg) a1 -= 100.f;
                s0[tI] = a0; s1[tI] = a1;
                mx0 = fmaxf(mx0, a0); mx1 = fmaxf(mx1, a1);
            }
        }
#pragma unroll
        for (int o = 16; o; o >>= 1) {
            mx0 = fmaxf(mx0, __shfl_xor_sync(0xffffffffu, mx0, o));
            mx1 = fmaxf(mx1, __shfl_xor_sync(0xffffffffu, mx1, o));
        }
        float sum0 = 0.f, sum1 = 0.f;
#pragma unroll
        for (int tI = 0; tI < 11; tI++) {
            int m = lane + 32 * tI;
            if (m < NTOK) {
                s0[tI] = __expf(s0[tI] - mx0); sum0 += s0[tI];
                s1[tI] = __expf(s1[tI] - mx1); sum1 += s1[tI];
            }
        }
#pragma unroll
        for (int o = 16; o; o >>= 1) {
            sum0 += __shfl_xor_sync(0xffffffffu, sum0, o);
            sum1 += __shfl_xor_sync(0xffffffffu, sum1, o);
        }
        float inv0 = 1.f / sum0, inv1 = 1.f / sum1;
#pragma unroll
        for (int tI = 0; tI < 11; tI++) {
            int m = lane + 32 * tI;
            if (m < NTOK) *(float2*)&spw[2 * m] = make_float2(s0[tI] * inv0, s1[tI] * inv1);
        }
        __syncwarp();
        const float2* pw = (const float2*)spw;
        float acc0 = 0.f, acc1 = 0.f;
#pragma unroll 7
        for (int m = 0; m < NTOK; m++) {
            float2 p = pw[m];
            float vv = sv[m * 36 + lane];
            acc0 += p.x * vv;
            acc1 += p.y * vv;
        }
        size_t ob = ((size_t)w * NTOK + i0) * DIM + h * HD + lane;
        attout[ob] = acc0;
        if (has1) attout[ob + DIM] = acc1;
        __syncwarp();
    }
}

// -------- launch --------
extern "C" void kernel_launch(void* const* d_in, const int* in_sizes, int n_in,
                              void* d_out, int out_size) {
    const float* x     = (const float*)d_in[0];
    const float* n1g   = (const float*)d_in[1];
    const float* n1b   = (const float*)d_in[2];
    const float* qkvw  = (const float*)d_in[3];
    const float* qkvb  = (const float*)d_in[4];
    const float* rel   = (const float*)d_in[5];
    const float* projw = (const float*)d_in[6];
    const float* projb = (const float*)d_in[7];
    const float* n2g   = (const float*)d_in[8];
    const float* n2b   = (const float*)d_in[9];
    const float* fc1w  = (const float*)d_in[10];
    const float* fc1b  = (const float*)d_in[11];
    const float* fc2w  = (const float*)d_in[12];
    const float* fc2b  = (const float*)d_in[13];
    float* out = (float*)d_out;

    float *xw, *qkvp, *att, *x1, *xn2; __half* hbuf;
    cudaGetSymbolAddress((void**)&xw,   g_xw);
    cudaGetSymbolAddress((void**)&qkvp, g_qkv);
    cudaGetSymbolAddress((void**)&att,  g_att);
    cudaGetSymbolAddress((void**)&x1,   g_x1);
    cudaGetSymbolAddress((void**)&xn2,  g_xn2);
    cudaGetSymbolAddress((void**)&hbuf, g_h);

    cudaFuncSetAttribute(attn_kernel, cudaFuncAttributeMaxDynamicSharedMemorySize, ATTN_SMEM);

    // 1) LN1 + shift + window partition
    ln_kernel<<<NROWS / 8, 256>>>(x, n1g, n1b, xw, 1);
    // 2) QKV GEMM (tensor core)
    mma_gemm<0, float, float><<<dim3(384 / BN, NROWS / BM), 256>>>(xw, qkvw, qkvb, nullptr, qkvp, NROWS, 384, 128);
    // 3) windowed attention
    attn_kernel<<<NWIN * NH, 512, ATTN_SMEM>>>(qkvp, rel, att);
    // 4) proj GEMM + window-reverse + unshift + residual
    mma_gemm<2, float, float><<<dim3(1, NROWS / BM), 256>>>(att, projw, projb, x, x1, NROWS, 128, 128);
    // 5) LN2
    ln_kernel<<<NROWS / 8, 256>>>(x1, n2g, n2b, xn2, 0);
    // 6) fc1 + GELU (writes fp16 hidden)
    mma_gemm<1, float, __half><<<dim3(512 / BN, NROWS / BM), 256>>>(xn2, fc1w, fc1b, nullptr, hbuf, NROWS, 512, 128);
    // 7) fc2 + residual -> output (reads fp16 hidden)
    mma_gemm<3, __half, float><<<dim3(1, NROWS / BM), 256>>>(hbuf, fc2w, fc2b, x1, out, NROWS, 128, 512);
}

// round 4
// speedup vs baseline: 4.7269x; 2.6381x over previous
#include <cuda_runtime.h>
#include <cuda_fp16.h>
#include <math.h>

#define DIM   128
#define NH    4
#define HD    32
#define WS    7
#define SS    3
#define ZP    14
#define HP    56
#define WP    56
#define NTOK  343
#define PADN  352
#define NWIN  256
#define NROWS (NWIN * NTOK)   // 87808
#define NMLP  512
#define QK_SCALE 0.17677669529663687f

// -------- scratch (static device globals) --------
__device__ __half g_xw [NROWS * DIM];
__device__ __half g_qkv[NROWS * 3 * DIM];
__device__ __half g_att[NROWS * DIM];
__device__ float  g_x1 [NROWS * DIM];
__device__ __half g_xn2[NROWS * DIM];
__device__ __half g_h  [NROWS * NMLP];
__device__ __half g_wh [196608];                       // fp16 weights: qkv|proj|fc1|fc2
__device__ __half g_btab[8 * NH * PADN * PADN];        // bias+mask table (7.9MB)

__device__ __forceinline__ int nat_row(int r) {
    int w = r / NTOK, t = r - w * NTOK;
    int b = w >> 7, wi = w & 127;
    int wz = wi >> 6, wy = (wi >> 3) & 7, wx = wi & 7;
    int lz = t / 49, rem = t - lz * 49, ly = rem / 7, lx = rem - ly * 7;
    int z = wz * WS + lz + SS; if (z >= ZP) z -= ZP;
    int y = wy * WS + ly + SS; if (y >= HP) y -= HP;
    int x = wx * WS + lx + SS; if (x >= WP) x -= WP;
    return ((b * ZP + z) * HP + y) * WP + x;
}

// -------- prologue: fp32 weights -> fp16 --------
__global__ void wconv_kernel(const float* __restrict__ qkvw, const float* __restrict__ projw,
                             const float* __restrict__ fc1w, const float* __restrict__ fc2w,
                             __half* __restrict__ o) {
    int i = blockIdx.x * 256 + threadIdx.x;
    float v;
    if (i < 49152) v = qkvw[i];
    else if (i < 65536) v = projw[i - 49152];
    else if (i < 131072) v = fc1w[i - 65536];
    else v = fc2w[i - 131072];
    o[i] = __float2half(v);
}

// -------- prologue: bias+mask table per (wtype, head) --------
__global__ void btab_kernel(const float* __restrict__ rel, __half* __restrict__ tab) {
    int idx = blockIdx.x * 256 + threadIdx.x;
    if (idx >= 8 * NH * PADN * PADN) return;
    int j = idx % PADN, t1 = idx / PADN;
    int i = t1 % PADN, t2 = t1 / PADN;
    int h = t2 & 3, wt = t2 >> 2;
    float val;
    if (i >= NTOK || j >= NTOK) val = -30000.f;
    else {
        int iz = i / 49, ir = i - iz * 49, iy = ir / 7, ix = ir - iy * 7;
        int jz = j / 49, jr = j - jz * 49, jy = jr / 7, jx = jr - jy * 7;
        int ridx = (iz - jz + 6) * 169 + (iy - jy + 6) * 13 + (ix - jx + 6);
        int ri = ((wt & 4) ? ((iz < 4) ? 1 : 2) : 0) * 9
               + ((wt & 2) ? ((iy < 4) ? 1 : 2) : 0) * 3
               + ((wt & 1) ? ((ix < 4) ? 1 : 2) : 0);
        int rj = ((wt & 4) ? ((jz < 4) ? 1 : 2) : 0) * 9
               + ((wt & 2) ? ((jy < 4) ? 1 : 2) : 0) * 3
               + ((wt & 1) ? ((jx < 4) ? 1 : 2) : 0);
        val = rel[ridx * NH + h] + ((ri == rj) ? 0.f : -100.f);
    }
    tab[idx] = __float2half(val);
}

// -------- LayerNorm: one warp per token, fp16 out --------
__global__ void ln_kernel(const float* __restrict__ src, const float* __restrict__ g,
                          const float* __restrict__ b, __half* __restrict__ dst, int gather) {
    int token = blockIdx.x * 8 + (threadIdx.x >> 5);
    int lane  = threadIdx.x & 31;
    int srow  = gather ? nat_row(token) : token;
    float4 v = ((const float4*)(src + (size_t)srow * DIM))[lane];
    float s  = v.x + v.y + v.z + v.w;
    float ss = v.x * v.x + v.y * v.y + v.z * v.z + v.w * v.w;
#pragma unroll
    for (int o = 16; o; o >>= 1) {
        s  += __shfl_xor_sync(0xffffffffu, s,  o);
        ss += __shfl_xor_sync(0xffffffffu, ss, o);
    }
    float mean = s * (1.f / 128.f);
    float inv  = rsqrtf(ss * (1.f / 128.f) - mean * mean + 1e-5f);
    float4 gg = ((const float4*)g)[lane];
    float4 bb = ((const float4*)b)[lane];
    __half2 h01 = __floats2half2_rn((v.x - mean) * inv * gg.x + bb.x,
                                    (v.y - mean) * inv * gg.y + bb.y);
    __half2 h23 = __floats2half2_rn((v.z - mean) * inv * gg.z + bb.z,
                                    (v.w - mean) * inv * gg.w + bb.w);
    __half2* d = (__half2*)(dst + (size_t)token * DIM);
    d[lane * 2] = h01; d[lane * 2 + 1] = h23;
}

// ================= MMA helpers =================
__device__ __forceinline__ void ldsm_x4(unsigned (&r)[4], unsigned addr) {
    asm volatile("ldmatrix.sync.aligned.m8n8.x4.shared.b16 {%0,%1,%2,%3}, [%4];"
                 : "=r"(r[0]), "=r"(r[1]), "=r"(r[2]), "=r"(r[3]) : "r"(addr));
}
__device__ __forceinline__ void ldsm_x4_t(unsigned (&r)[4], unsigned addr) {
    asm volatile("ldmatrix.sync.aligned.m8n8.x4.trans.shared.b16 {%0,%1,%2,%3}, [%4];"
                 : "=r"(r[0]), "=r"(r[1]), "=r"(r[2]), "=r"(r[3]) : "r"(addr));
}
__device__ __forceinline__ void mma16816(float (&c)[4], const unsigned (&a)[4],
                                         unsigned b0, unsigned b1) {
    asm volatile("mma.sync.aligned.m16n8k16.row.col.f32.f16.f16.f32 "
                 "{%0,%1,%2,%3},{%4,%5,%6,%7},{%8,%9},{%0,%1,%2,%3};"
                 : "+f"(c[0]), "+f"(c[1]), "+f"(c[2]), "+f"(c[3])
                 : "r"(a[0]), "r"(a[1]), "r"(a[2]), "r"(a[3]), "r"(b0), "r"(b1));
}
__device__ __forceinline__ void cpa16(unsigned dst, const void* src) {
    asm volatile("cp.async.cg.shared.global [%0], [%1], 16;" :: "r"(dst), "l"(src));
}
__device__ __forceinline__ void cpa_commit() { asm volatile("cp.async.commit_group;"); }
template <int N> __device__ __forceinline__ void cpa_wait() {
    asm volatile("cp.async.wait_group %0;" :: "n"(N));
}

// ================= tensor-core GEMM, cp.async 3-stage =================
// BM=128, BN=128, BK=32, 256 thr, warp tile 64x32. A,B fp16 in gmem.
#define BK 32
#define STG_A (128 * 40)            // halfs
#define STG_B (BK * 136)
#define STG_TOT (STG_A + STG_B)
#define GEMM_SMEM (3 * STG_TOT * 2) // bytes

template <int EPI, typename CT>
__global__ void __launch_bounds__(256, 2) mma_gemm(
        const __half* __restrict__ A, const __half* __restrict__ B,
        const float* __restrict__ bias, const float* __restrict__ res,
        CT* __restrict__ C, int M, int N, int K) {
    extern __shared__ __half gsm[];
    const int tid  = threadIdx.x;
    const int lane = tid & 31, warp = tid >> 5;
    const int mw = warp >> 2, nw = warp & 3;
    const int bm = blockIdx.y * 128, bn = blockIdx.x * 128;

    const int arow = tid >> 1, ac0 = (tid & 1) * 16;
    const int brow = tid >> 3, bc0 = (tid & 7) * 16;
    const unsigned smbase = (unsigned)__cvta_generic_to_shared(gsm);

    float acc[4][4][4];
#pragma unroll
    for (int i = 0; i < 4; i++)
#pragma unroll
        for (int j = 0; j < 4; j++)
#pragma unroll
            for (int l = 0; l < 4; l++) acc[i][j][l] = 0.f;

    const int niter = K / BK;
    auto issue = [&](int it) {
        int s = it % 3;
        unsigned da = smbase + (s * STG_TOT + arow * 40 + ac0) * 2;
        const __half* pa = A + (size_t)(bm + arow) * K + it * BK + ac0;
        cpa16(da, pa); cpa16(da + 16, pa + 8);
        unsigned db = smbase + (s * STG_TOT + STG_A + brow * 136 + bc0) * 2;
        const __half* pb = B + (size_t)(it * BK + brow) * N + bn + bc0;
        cpa16(db, pb); cpa16(db + 16, pb + 8);
        cpa_commit();
    };
    issue(0); issue(1);

    const unsigned aLane = ((lane & 15) * 40 + (lane >> 4) * 8) * 2 + (unsigned)(mw * 64 * 40 * 2);
    const unsigned bLane = (((lane & 7) + ((lane >> 3) & 1) * 8) * 136 + (lane >> 4) * 8) * 2
                           + (unsigned)(nw * 32 * 2);

    for (int it = 0; it < niter; it++) {
        cpa_wait<1>();
        __syncthreads();
        if (it + 2 < niter) issue(it + 2);
        int s = it % 3;
        unsigned aBase = smbase + s * STG_TOT * 2 + aLane;
        unsigned bBase = smbase + (s * STG_TOT + STG_A) * 2 + bLane;
#pragma unroll
        for (int ks = 0; ks < 2; ks++) {
            unsigned a[4][4], b[2][4];
#pragma unroll
            for (int mf = 0; mf < 4; mf++) ldsm_x4(a[mf], aBase + mf * (16 * 40 * 2) + ks * 32);
#pragma unroll
            for (int np = 0; np < 2; np++) ldsm_x4_t(b[np], bBase + np * 32 + ks * (16 * 136 * 2));
#pragma unroll
            for (int mf = 0; mf < 4; mf++)
#pragma unroll
                for (int nf = 0; nf < 4; nf++)
                    mma16816(acc[mf][nf], a[mf], b[nf >> 1][(nf & 1) * 2],
                             b[nf >> 1][(nf & 1) * 2 + 1]);
        }
        __syncthreads();
    }

#pragma unroll
    for (int mf = 0; mf < 4; mf++) {
        int r0 = bm + mw * 64 + mf * 16 + (lane >> 2);
        int r1 = r0 + 8;
        int or0 = (EPI == 2) ? nat_row(r0) : r0;
        int or1 = (EPI == 2) ? nat_row(r1) : r1;
#pragma unroll
        for (int nf = 0; nf < 4; nf++) {
            int c = bn + nw * 32 + nf * 8 + (lane & 3) * 2;
            float bv0 = bias[c], bv1 = bias[c + 1];
            float v00 = acc[mf][nf][0] + bv0, v01 = acc[mf][nf][1] + bv1;
            float v10 = acc[mf][nf][2] + bv0, v11 = acc[mf][nf][3] + bv1;
            if (EPI == 1) {
                v00 = 0.5f * v00 * (1.f + erff(v00 * 0.7071067811865475f));
                v01 = 0.5f * v01 * (1.f + erff(v01 * 0.7071067811865475f));
                v10 = 0.5f * v10 * (1.f + erff(v10 * 0.7071067811865475f));
                v11 = 0.5f * v11 * (1.f + erff(v11 * 0.7071067811865475f));
            }
            if (EPI == 2) {
                v00 += res[(size_t)or0 * DIM + c];   v01 += res[(size_t)or0 * DIM + c + 1];
                v10 += res[(size_t)or1 * DIM + c];   v11 += res[(size_t)or1 * DIM + c + 1];
            }
            if (EPI == 3) {
                v00 += res[(size_t)r0 * DIM + c];    v01 += res[(size_t)r0 * DIM + c + 1];
                v10 += res[(size_t)r1 * DIM + c];    v11 += res[(size_t)r1 * DIM + c + 1];
            }
            if constexpr (sizeof(CT) == 2) {
                *(__half2*)((__half*)C + (size_t)or0 * N + c) = __floats2half2_rn(v00, v01);
                *(__half2*)((__half*)C + (size_t)or1 * N + c) = __floats2half2_rn(v10, v11);
            } else {
                *(float2*)((float*)C + (size_t)or0 * N + c) = make_float2(v00, v01);
                *(float2*)((float*)C + (size_t)or1 * N + c) = make_float2(v10, v11);
            }
        }
    }
}

// ================= FA2-style windowed attention (fp16 mma) =================
// CTA = (window, head). smem: Q,K,V [352][40] halfs = 84,480 B.
#define ATTN_SMEM (3 * PADN * 40 * 2)

__global__ void __launch_bounds__(256) attn_kernel(
        const __half* __restrict__ qkv, const __half* __restrict__ tab,
        __half* __restrict__ attout) {
    extern __shared__ __half asm_[];
    __half* sQ = asm_;
    __half* sK = asm_ + PADN * 40;
    __half* sV = asm_ + 2 * PADN * 40;

    const int w = blockIdx.x >> 2, h = blockIdx.x & 3;
    const int tid = threadIdx.x, lane = tid & 31, warp = tid >> 5;

    // stage Q,K,V (half, 16B chunks); zero pad rows
    for (int idx = tid; idx < PADN * 4; idx += 256) {
        int t = idx >> 2, c = (idx & 3) * 8;
        uint4 zq = {0,0,0,0}, zk = zq, zv = zq;
        if (t < NTOK) {
            const __half* base = qkv + (size_t)(w * NTOK + t) * (3 * DIM) + h * HD + c;
            zq = *(const uint4*)base;
            zk = *(const uint4*)(base + DIM);
            zv = *(const uint4*)(base + 2 * DIM);
        }
        *(uint4*)&sQ[t * 40 + c] = zq;
        *(uint4*)&sK[t * 40 + c] = zk;
        *(uint4*)&sV[t * 40 + c] = zv;
    }
    __syncthreads();

    const int wi = w & 127;
    const int wt = (((wi >> 6) & 1) << 2) | ((((wi >> 3) & 7) == 7) ? 2 : 0) | (((wi & 7) == 7) ? 1 : 0);
    const __half* tb = tab + (size_t)(wt * NH + h) * PADN * PADN;
    const unsigned smb = (unsigned)__cvta_generic_to_shared(asm_);
    const unsigned kvRow = (unsigned)((lane & 7) + ((lane >> 4) & 1) * 8);
    const unsigned kvCol = (unsigned)(((lane >> 3) & 1) * 8);
    const unsigned vRow  = (unsigned)((lane & 7) + ((lane >> 3) & 1) * 8);
    const unsigned vCol  = (unsigned)((lane >> 4) * 8);

    for (int mt = warp; mt < 22; mt += 8) {
        const int m0 = mt * 16;
        unsigned aq[2][4];
        {
            unsigned aAddr = smb + ((m0 + (lane & 15)) * 40 + (lane >> 4) * 8) * 2;
            ldsm_x4(aq[0], aAddr);
            ldsm_x4(aq[1], aAddr + 32);
        }
        const int r0g = m0 + (lane >> 2), r1g = r0g + 8;
        const __half* tr0 = tb + (size_t)r0g * PADN;
        const __half* tr1 = tb + (size_t)r1g * PADN;

        float o[4][4];
#pragma unroll
        for (int i = 0; i < 4; i++)
#pragma unroll
            for (int j = 0; j < 4; j++) o[i][j] = 0.f;
        float mx0 = -1e30f, mx1 = -1e30f, l0 = 0.f, l1 = 0.f;

        for (int n0 = 0; n0 < PADN; n0 += 16) {
            // S = Q K^T (two 16x8 tiles)
            float s[2][4] = {{0,0,0,0},{0,0,0,0}};
            unsigned kf0[4], kf1[4];
            unsigned kAddr = smb + (PADN * 40 + (n0 + kvRow) * 40 + kvCol) * 2;
            ldsm_x4(kf0, kAddr);           // k 0..15
            ldsm_x4(kf1, kAddr + 32);      // k 16..31
            mma16816(s[0], aq[0], kf0[0], kf0[1]);
            mma16816(s[0], aq[1], kf1[0], kf1[1]);
            mma16816(s[1], aq[0], kf0[2], kf0[3]);
            mma16816(s[1], aq[1], kf1[2], kf1[3]);

            // bias+mask (+ fold QK scale)
            int jc = n0 + (lane & 3) * 2;
#pragma unroll
            for (int nt = 0; nt < 2; nt++) {
                float2 b0 = __half22float2(*(const __half2*)(tr0 + jc + nt * 8));
                float2 b1 = __half22float2(*(const __half2*)(tr1 + jc + nt * 8));
                s[nt][0] = s[nt][0] * QK_SCALE + b0.x;
                s[nt][1] = s[nt][1] * QK_SCALE + b0.y;
                s[nt][2] = s[nt][2] * QK_SCALE + b1.x;
                s[nt][3] = s[nt][3] * QK_SCALE + b1.y;
            }

            // online softmax
            float cm0 = fmaxf(fmaxf(s[0][0], s[0][1]), fmaxf(s[1][0], s[1][1]));
            float cm1 = fmaxf(fmaxf(s[0][2], s[0][3]), fmaxf(s[1][2], s[1][3]));
#pragma unroll
            for (int ofs = 1; ofs <= 2; ofs <<= 1) {
                cm0 = fmaxf(cm0, __shfl_xor_sync(0xffffffffu, cm0, ofs));
                cm1 = fmaxf(cm1, __shfl_xor_sync(0xffffffffu, cm1, ofs));
            }
            float nm0 = fmaxf(mx0, cm0), nm1 = fmaxf(mx1, cm1);
            float al0 = __expf(mx0 - nm0), al1 = __expf(mx1 - nm1);
            mx0 = nm0; mx1 = nm1;
#pragma unroll
            for (int nf = 0; nf < 4; nf++) {
                o[nf][0] *= al0; o[nf][1] *= al0;
                o[nf][2] *= al1; o[nf][3] *= al1;
            }
#pragma unroll
            for (int nt = 0; nt < 2; nt++) {
                s[nt][0] = __expf(s[nt][0] - nm0);
                s[nt][1] = __expf(s[nt][1] - nm0);
                s[nt][2] = __expf(s[nt][2] - nm1);
                s[nt][3] = __expf(s[nt][3] - nm1);
            }
            float ps0 = s[0][0] + s[0][1] + s[1][0] + s[1][1];
            float ps1 = s[0][2] + s[0][3] + s[1][2] + s[1][3];
#pragma unroll
            for (int ofs = 1; ofs <= 2; ofs <<= 1) {
                ps0 += __shfl_xor_sync(0xffffffffu, ps0, ofs);
                ps1 += __shfl_xor_sync(0xffffffffu, ps1, ofs);
            }
            l0 = l0 * al0 + ps0;
            l1 = l1 * al1 + ps1;

            // P fragment (C->A register reuse)
            unsigned pa[4];
            __half2 p0 = __floats2half2_rn(s[0][0], s[0][1]);
            __half2 p1 = __floats2half2_rn(s[0][2], s[0][3]);
            __half2 p2 = __floats2half2_rn(s[1][0], s[1][1]);
            __half2 p3 = __floats2half2_rn(s[1][2], s[1][3]);
            pa[0] = *(unsigned*)&p0; pa[1] = *(unsigned*)&p1;
            pa[2] = *(unsigned*)&p2; pa[3] = *(unsigned*)&p3;

            // O += P V
            unsigned vf0[4], vf1[4];
            unsigned vAddr = smb + (2 * PADN * 40 + (n0 + vRow) * 40 + vCol) * 2;
            ldsm_x4_t(vf0, vAddr);
            ldsm_x4_t(vf1, vAddr + 32);
            mma16816(o[0], pa, vf0[0], vf0[1]);
            mma16816(o[1], pa, vf0[2], vf0[3]);
            mma16816(o[2], pa, vf1[0], vf1[1]);
            mma16816(o[3], pa, vf1[2], vf1[3]);
        }

        float inv0 = 1.f / l0, inv1 = 1.f / l1;
        int cbase = h * HD + (lane & 3) * 2;
        if (r0g < NTOK) {
            __half* dst = attout + (size_t)(w * NTOK + r0g) * DIM + cbase;
#pragma unroll
            for (int nf = 0; nf < 4; nf++)
                *(__half2*)(dst + nf * 8) = __floats2half2_rn(o[nf][0] * inv0, o[nf][1] * inv0);
        }
        if (r1g < NTOK) {
            __half* dst = attout + (size_t)(w * NTOK + r1g) * DIM + cbase;
#pragma unroll
            for (int nf = 0; nf < 4; nf++)
                *(__half2*)(dst + nf * 8) = __floats2half2_rn(o[nf][2] * inv1, o[nf][3] * inv1);
        }
    }
}

// -------- launch --------
extern "C" void kernel_launch(void* const* d_in, const int* in_sizes, int n_in,
                              void* d_out, int out_size) {
    const float* x     = (const float*)d_in[0];
    const float* n1g   = (const float*)d_in[1];
    const float* n1b   = (const float*)d_in[2];
    const float* qkvw  = (const float*)d_in[3];
    const float* qkvb  = (const float*)d_in[4];
    const float* rel   = (const float*)d_in[5];
    const float* projw = (const float*)d_in[6];
    const float* projb = (const float*)d_in[7];
    const float* n2g   = (const float*)d_in[8];
    const float* n2b   = (const float*)d_in[9];
    const float* fc1w  = (const float*)d_in[10];
    const float* fc1b  = (const float*)d_in[11];
    const float* fc2w  = (const float*)d_in[12];
    const float* fc2b  = (const float*)d_in[13];
    float* out = (float*)d_out;

    __half *xw, *qkvp, *att, *xn2, *hbuf, *wh, *btab;
    float *x1;
    cudaGetSymbolAddress((void**)&xw,   g_xw);
    cudaGetSymbolAddress((void**)&qkvp, g_qkv);
    cudaGetSymbolAddress((void**)&att,  g_att);
    cudaGetSymbolAddress((void**)&x1,   g_x1);
    cudaGetSymbolAddress((void**)&xn2,  g_xn2);
    cudaGetSymbolAddress((void**)&hbuf, g_h);
    cudaGetSymbolAddress((void**)&wh,   g_wh);
    cudaGetSymbolAddress((void**)&btab, g_btab);

    cudaFuncSetAttribute(attn_kernel, cudaFuncAttributeMaxDynamicSharedMemorySize, ATTN_SMEM);
    cudaFuncSetAttribute(mma_gemm<0, __half>, cudaFuncAttributeMaxDynamicSharedMemorySize, GEMM_SMEM);
    cudaFuncSetAttribute(mma_gemm<1, __half>, cudaFuncAttributeMaxDynamicSharedMemorySize, GEMM_SMEM);
    cudaFuncSetAttribute(mma_gemm<2, float>,  cudaFuncAttributeMaxDynamicSharedMemorySize, GEMM_SMEM);
    cudaFuncSetAttribute(mma_gemm<3, float>,  cudaFuncAttributeMaxDynamicSharedMemorySize, GEMM_SMEM);

    // prologues
    wconv_kernel<<<768, 256>>>(qkvw, projw, fc1w, fc2w, wh);
    btab_kernel<<<(8 * NH * PADN * PADN + 255) / 256, 256>>>(rel, btab);
    // 1) LN1 + shift + window partition
    ln_kernel<<<NROWS / 8, 256>>>(x, n1g, n1b, xw, 1);
    // 2) QKV GEMM
    mma_gemm<0, __half><<<dim3(3, NROWS / 128), 256, GEMM_SMEM>>>(xw, wh, qkvb, nullptr, qkvp, NROWS, 384, 128);
    // 3) attention
    attn_kernel<<<NWIN * NH, 256, ATTN_SMEM>>>(qkvp, btab, att);
    // 4) proj + window-reverse + residual
    mma_gemm<2, float><<<dim3(1, NROWS / 128), 256, GEMM_SMEM>>>(att, wh + 49152, projb, x, x1, NROWS, 128, 128);
    // 5) LN2
    ln_kernel<<<NROWS / 8, 256>>>(x1, n2g, n2b, xn2, 0);
    // 6) fc1 + GELU
    mma_gemm<1, __half><<<dim3(4, NROWS / 128), 256, GEMM_SMEM>>>(xn2, wh + 65536, fc1b, nullptr, hbuf, NROWS, 512, 128);
    // 7) fc2 + residual -> out
    mma_gemm<3, float><<<dim3(1, NROWS / 128), 256, GEMM_SMEM>>>(hbuf, wh + 131072, fc2b, x1, out, NROWS, 128, 512);
}

// round 5
// speedup vs baseline: 4.8739x; 1.0311x over previous
#include <cuda_runtime.h>
#include <cuda_fp16.h>
#include <math.h>

#define DIM   128
#define NH    4
#define HD    32
#define WS    7
#define SS    3
#define ZP    14
#define HP    56
#define WP    56
#define NTOK  343
#define PADN  352
#define NWIN  256
#define NROWS (NWIN * NTOK)   // 87808
#define NMLP  512
#define QK_SCALE 0.17677669529663687f

// -------- scratch (static device globals) --------
__device__ __half g_xw [NROWS * DIM];
__device__ __half g_qkv[NROWS * 3 * DIM];
__device__ __half g_att[NROWS * DIM];
__device__ float  g_x1 [NROWS * DIM];
__device__ __half g_xn2[NROWS * DIM];
__device__ __half g_h  [NROWS * NMLP];
__device__ __half g_wh [196608];                       // fp16 weights: qkv|proj|fc1|fc2
__device__ __half g_btab[8 * NH * PADN * PADN];        // bias+mask table (7.9MB)

__device__ __forceinline__ int nat_row(int r) {
    int w = r / NTOK, t = r - w * NTOK;
    int b = w >> 7, wi = w & 127;
    int wz = wi >> 6, wy = (wi >> 3) & 7, wx = wi & 7;
    int lz = t / 49, rem = t - lz * 49, ly = rem / 7, lx = rem - ly * 7;
    int z = wz * WS + lz + SS; if (z >= ZP) z -= ZP;
    int y = wy * WS + ly + SS; if (y >= HP) y -= HP;
    int x = wx * WS + lx + SS; if (x >= WP) x -= WP;
    return ((b * ZP + z) * HP + y) * WP + x;
}

// -------- prologue: fp32 weights -> fp16 --------
__global__ void wconv_kernel(const float* __restrict__ qkvw, const float* __restrict__ projw,
                             const float* __restrict__ fc1w, const float* __restrict__ fc2w,
                             __half* __restrict__ o) {
    int i = blockIdx.x * 256 + threadIdx.x;
    float v;
    if (i < 49152) v = qkvw[i];
    else if (i < 65536) v = projw[i - 49152];
    else if (i < 131072) v = fc1w[i - 65536];
    else v = fc2w[i - 131072];
    o[i] = __float2half(v);
}

// -------- prologue: bias+mask table per (wtype, head) --------
__global__ void btab_kernel(const float* __restrict__ rel, __half* __restrict__ tab) {
    int idx = blockIdx.x * 256 + threadIdx.x;
    if (idx >= 8 * NH * PADN * PADN) return;
    int j = idx % PADN, t1 = idx / PADN;
    int i = t1 % PADN, t2 = t1 / PADN;
    int h = t2 & 3, wt = t2 >> 2;
    float val;
    if (i >= NTOK || j >= NTOK) val = -30000.f;
    else {
        int iz = i / 49, ir = i - iz * 49, iy = ir / 7, ix = ir - iy * 7;
        int jz = j / 49, jr = j - jz * 49, jy = jr / 7, jx = jr - jy * 7;
        int ridx = (iz - jz + 6) * 169 + (iy - jy + 6) * 13 + (ix - jx + 6);
        int ri = ((wt & 4) ? ((iz < 4) ? 1 : 2) : 0) * 9
               + ((wt & 2) ? ((iy < 4) ? 1 : 2) : 0) * 3
               + ((wt & 1) ? ((ix < 4) ? 1 : 2) : 0);
        int rj = ((wt & 4) ? ((jz < 4) ? 1 : 2) : 0) * 9
               + ((wt & 2) ? ((jy < 4) ? 1 : 2) : 0) * 3
               + ((wt & 1) ? ((jx < 4) ? 1 : 2) : 0);
        val = rel[ridx * NH + h] + ((ri == rj) ? 0.f : -100.f);
    }
    tab[idx] = __float2half(val);
}

// -------- LayerNorm: one warp per token, fp16 out --------
__global__ void ln_kernel(const float* __restrict__ src, const float* __restrict__ g,
                          const float* __restrict__ b, __half* __restrict__ dst, int gather) {
    int token = blockIdx.x * 8 + (threadIdx.x >> 5);
    int lane  = threadIdx.x & 31;
    int srow  = gather ? nat_row(token) : token;
    float4 v = ((const float4*)(src + (size_t)srow * DIM))[lane];
    float s  = v.x + v.y + v.z + v.w;
    float ss = v.x * v.x + v.y * v.y + v.z * v.z + v.w * v.w;
#pragma unroll
    for (int o = 16; o; o >>= 1) {
        s  += __shfl_xor_sync(0xffffffffu, s,  o);
        ss += __shfl_xor_sync(0xffffffffu, ss, o);
    }
    float mean = s * (1.f / 128.f);
    float inv  = rsqrtf(ss * (1.f / 128.f) - mean * mean + 1e-5f);
    float4 gg = ((const float4*)g)[lane];
    float4 bb = ((const float4*)b)[lane];
    __half2 h01 = __floats2half2_rn((v.x - mean) * inv * gg.x + bb.x,
                                    (v.y - mean) * inv * gg.y + bb.y);
    __half2 h23 = __floats2half2_rn((v.z - mean) * inv * gg.z + bb.z,
                                    (v.w - mean) * inv * gg.w + bb.w);
    __half2* d = (__half2*)(dst + (size_t)token * DIM);
    d[lane * 2] = h01; d[lane * 2 + 1] = h23;
}

// ================= MMA helpers =================
__device__ __forceinline__ void ldsm_x4(unsigned (&r)[4], unsigned addr) {
    asm volatile("ldmatrix.sync.aligned.m8n8.x4.shared.b16 {%0,%1,%2,%3}, [%4];"
                 : "=r"(r[0]), "=r"(r[1]), "=r"(r[2]), "=r"(r[3]) : "r"(addr));
}
__device__ __forceinline__ void ldsm_x4_t(unsigned (&r)[4], unsigned addr) {
    asm volatile("ldmatrix.sync.aligned.m8n8.x4.trans.shared.b16 {%0,%1,%2,%3}, [%4];"
                 : "=r"(r[0]), "=r"(r[1]), "=r"(r[2]), "=r"(r[3]) : "r"(addr));
}
__device__ __forceinline__ void mma16816(float (&c)[4], const unsigned (&a)[4],
                                         unsigned b0, unsigned b1) {
    asm volatile("mma.sync.aligned.m16n8k16.row.col.f32.f16.f16.f32 "
                 "{%0,%1,%2,%3},{%4,%5,%6,%7},{%8,%9},{%0,%1,%2,%3};"
                 : "+f"(c[0]), "+f"(c[1]), "+f"(c[2]), "+f"(c[3])
                 : "r"(a[0]), "r"(a[1]), "r"(a[2]), "r"(a[3]), "r"(b0), "r"(b1));
}
__device__ __forceinline__ void cpa16(unsigned dst, const void* src) {
    asm volatile("cp.async.cg.shared.global [%0], [%1], 16;" :: "r"(dst), "l"(src));
}
__device__ __forceinline__ void cpa_commit() { asm volatile("cp.async.commit_group;"); }
template <int N> __device__ __forceinline__ void cpa_wait() {
    asm volatile("cp.async.wait_group %0;" :: "n"(N));
}

// ================= tensor-core GEMM, cp.async 4-stage =================
// BM=128, BN=128, BK=32, 256 thr, warp tile 64x32. A,B fp16 in gmem.
#define BK 32
#define STG_A (128 * 40)            // halfs
#define STG_B (BK * 136)
#define STG_TOT (STG_A + STG_B)
#define GEMM_SMEM (4 * STG_TOT * 2) // 75,776 bytes

template <int EPI, typename CT>
__global__ void __launch_bounds__(256, 2) mma_gemm(
        const __half* __restrict__ A, const __half* __restrict__ B,
        const float* __restrict__ bias, const float* __restrict__ res,
        CT* __restrict__ C, int M, int N, int K) {
    extern __shared__ __half gsm[];
    const int tid  = threadIdx.x;
    const int lane = tid & 31, warp = tid >> 5;
    const int mw = warp >> 2, nw = warp & 3;
    const int bm = blockIdx.y * 128, bn = blockIdx.x * 128;

    const int arow = tid >> 1, ac0 = (tid & 1) * 16;
    const int brow = tid >> 3, bc0 = (tid & 7) * 16;
    const unsigned smbase = (unsigned)__cvta_generic_to_shared(gsm);

    float acc[4][4][4];
#pragma unroll
    for (int i = 0; i < 4; i++)
#pragma unroll
        for (int j = 0; j < 4; j++)
#pragma unroll
            for (int l = 0; l < 4; l++) acc[i][j][l] = 0.f;

    const int niter = K / BK;
    auto issue = [&](int it) {
        int s = it & 3;
        unsigned da = smbase + (s * STG_TOT + arow * 40 + ac0) * 2;
        const __half* pa = A + (size_t)(bm + arow) * K + it * BK + ac0;
        cpa16(da, pa); cpa16(da + 16, pa + 8);
        unsigned db = smbase + (s * STG_TOT + STG_A + brow * 136 + bc0) * 2;
        const __half* pb = B + (size_t)(it * BK + brow) * N + bn + bc0;
        cpa16(db, pb); cpa16(db + 16, pb + 8);
        cpa_commit();
    };
    issue(0);
    if (niter > 1) issue(1); else cpa_commit();
    if (niter > 2) issue(2); else cpa_commit();

    const unsigned aLane = ((lane & 15) * 40 + (lane >> 4) * 8) * 2 + (unsigned)(mw * 64 * 40 * 2);
    const unsigned bLane = (((lane & 7) + ((lane >> 3) & 1) * 8) * 136 + (lane >> 4) * 8) * 2
                           + (unsigned)(nw * 32 * 2);

    for (int it = 0; it < niter; it++) {
        if (it + 3 < niter) issue(it + 3); else cpa_commit();
        cpa_wait<3>();            // oldest group (it) retired; 3 in flight
        __syncthreads();
        int s = it & 3;
        unsigned aBase = smbase + s * STG_TOT * 2 + aLane;
        unsigned bBase = smbase + (s * STG_TOT + STG_A) * 2 + bLane;
#pragma unroll
        for (int ks = 0; ks < 2; ks++) {
            unsigned a[4][4], b[2][4];
#pragma unroll
            for (int mf = 0; mf < 4; mf++) ldsm_x4(a[mf], aBase + mf * (16 * 40 * 2) + ks * 32);
#pragma unroll
            for (int np = 0; np < 2; np++) ldsm_x4_t(b[np], bBase + np * 32 + ks * (16 * 136 * 2));
#pragma unroll
            for (int mf = 0; mf < 4; mf++)
#pragma unroll
                for (int nf = 0; nf < 4; nf++)
                    mma16816(acc[mf][nf], a[mf], b[nf >> 1][(nf & 1) * 2],
                             b[nf >> 1][(nf & 1) * 2 + 1]);
        }
        __syncthreads();          // reads done before stage reuse
    }

#pragma unroll
    for (int mf = 0; mf < 4; mf++) {
        int r0 = bm + mw * 64 + mf * 16 + (lane >> 2);
        int r1 = r0 + 8;
        int or0 = (EPI == 2) ? nat_row(r0) : r0;
        int or1 = (EPI == 2) ? nat_row(r1) : r1;
#pragma unroll
        for (int nf = 0; nf < 4; nf++) {
            int c = bn + nw * 32 + nf * 8 + (lane & 3) * 2;
            float bv0 = bias[c], bv1 = bias[c + 1];
            float v00 = acc[mf][nf][0] + bv0, v01 = acc[mf][nf][1] + bv1;
            float v10 = acc[mf][nf][2] + bv0, v11 = acc[mf][nf][3] + bv1;
            if (EPI == 1) {
                v00 = 0.5f * v00 * (1.f + erff(v00 * 0.7071067811865475f));
                v01 = 0.5f * v01 * (1.f + erff(v01 * 0.7071067811865475f));
                v10 = 0.5f * v10 * (1.f + erff(v10 * 0.7071067811865475f));
                v11 = 0.5f * v11 * (1.f + erff(v11 * 0.7071067811865475f));
            }
            if (EPI == 2) {
                v00 += res[(size_t)or0 * DIM + c];   v01 += res[(size_t)or0 * DIM + c + 1];
                v10 += res[(size_t)or1 * DIM + c];   v11 += res[(size_t)or1 * DIM + c + 1];
            }
            if (EPI == 3) {
                v00 += res[(size_t)r0 * DIM + c];    v01 += res[(size_t)r0 * DIM + c + 1];
                v10 += res[(size_t)r1 * DIM + c];    v11 += res[(size_t)r1 * DIM + c + 1];
            }
            if constexpr (sizeof(CT) == 2) {
                *(__half2*)((__half*)C + (size_t)or0 * N + c) = __floats2half2_rn(v00, v01);
                *(__half2*)((__half*)C + (size_t)or1 * N + c) = __floats2half2_rn(v10, v11);
            } else {
                *(float2*)((float*)C + (size_t)or0 * N + c) = make_float2(v00, v01);
                *(float2*)((float*)C + (size_t)or1 * N + c) = make_float2(v10, v11);
            }
        }
    }
}

// ================= FA2-style windowed attention (fp16 mma) =================
// CTA = (window, head). smem: Q,K,V [352][40] halfs = 84,480 B. 2 CTAs/SM.
#define ATTN_SMEM (3 * PADN * 40 * 2)

__global__ void __launch_bounds__(256, 2) attn_kernel(
        const __half* __restrict__ qkv, const __half* __restrict__ tab,
        __half* __restrict__ attout) {
    extern __shared__ __half asm_[];
    __half* sQ = asm_;
    __half* sK = asm_ + PADN * 40;
    __half* sV = asm_ + 2 * PADN * 40;

    const int w = blockIdx.x >> 2, h = blockIdx.x & 3;
    const int tid = threadIdx.x, lane = tid & 31, warp = tid >> 5;

    // stage Q,K,V (half, 16B chunks); zero pad rows
    for (int idx = tid; idx < PADN * 4; idx += 256) {
        int t = idx >> 2, c = (idx & 3) * 8;
        uint4 zq = {0,0,0,0}, zk = zq, zv = zq;
        if (t < NTOK) {
            const __half* base = qkv + (size_t)(w * NTOK + t) * (3 * DIM) + h * HD + c;
            zq = *(const uint4*)base;
            zk = *(const uint4*)(base + DIM);
            zv = *(const uint4*)(base + 2 * DIM);
        }
        *(uint4*)&sQ[t * 40 + c] = zq;
        *(uint4*)&sK[t * 40 + c] = zk;
        *(uint4*)&sV[t * 40 + c] = zv;
    }
    __syncthreads();

    const int wi = w & 127;
    const int wt = (((wi >> 6) & 1) << 2) | ((((wi >> 3) & 7) == 7) ? 2 : 0) | (((wi & 7) == 7) ? 1 : 0);
    const __half* tb = tab + (size_t)(wt * NH + h) * PADN * PADN;
    const unsigned smb = (unsigned)__cvta_generic_to_shared(asm_);
    const unsigned kvRow = (unsigned)((lane & 7) + ((lane >> 4) & 1) * 8);
    const unsigned kvCol = (unsigned)(((lane >> 3) & 1) * 8);
    const unsigned vRow  = (unsigned)((lane & 7) + ((lane >> 3) & 1) * 8);
    const unsigned vCol  = (unsigned)((lane >> 4) * 8);

    for (int mt = warp; mt < 22; mt += 8) {
        const int m0 = mt * 16;
        unsigned aq[2][4];
        {
            unsigned aAddr = smb + ((m0 + (lane & 15)) * 40 + (lane >> 4) * 8) * 2;
            ldsm_x4(aq[0], aAddr);
            ldsm_x4(aq[1], aAddr + 32);
        }
        const int r0g = m0 + (lane >> 2), r1g = r0g + 8;
        const __half* tr0 = tb + (size_t)r0g * PADN;
        const __half* tr1 = tb + (size_t)r1g * PADN;

        float o[4][4];
#pragma unroll
        for (int i = 0; i < 4; i++)
#pragma unroll
            for (int j = 0; j < 4; j++) o[i][j] = 0.f;
        float mx0 = -1e30f, mx1 = -1e30f, l0 = 0.f, l1 = 0.f;

        for (int n0 = 0; n0 < PADN; n0 += 16) {
            // S = Q K^T (two 16x8 tiles)
            float s[2][4] = {{0,0,0,0},{0,0,0,0}};
            unsigned kf0[4], kf1[4];
            unsigned kAddr = smb + (PADN * 40 + (n0 + kvRow) * 40 + kvCol) * 2;
            ldsm_x4(kf0, kAddr);           // k 0..15
            ldsm_x4(kf1, kAddr + 32);      // k 16..31
            mma16816(s[0], aq[0], kf0[0], kf0[1]);
            mma16816(s[0], aq[1], kf1[0], kf1[1]);
            mma16816(s[1], aq[0], kf0[2], kf0[3]);
            mma16816(s[1], aq[1], kf1[2], kf1[3]);

            // bias+mask (+ fold QK scale)
            int jc = n0 + (lane & 3) * 2;
#pragma unroll
            for (int nt = 0; nt < 2; nt++) {
                float2 b0 = __half22float2(*(const __half2*)(tr0 + jc + nt * 8));
                float2 b1 = __half22float2(*(const __half2*)(tr1 + jc + nt * 8));
                s[nt][0] = s[nt][0] * QK_SCALE + b0.x;
                s[nt][1] = s[nt][1] * QK_SCALE + b0.y;
                s[nt][2] = s[nt][2] * QK_SCALE + b1.x;
                s[nt][3] = s[nt][3] * QK_SCALE + b1.y;
            }

            // online softmax
            float cm0 = fmaxf(fmaxf(s[0][0], s[0][1]), fmaxf(s[1][0], s[1][1]));
            float cm1 = fmaxf(fmaxf(s[0][2], s[0][3]), fmaxf(s[1][2], s[1][3]));
#pragma unroll
            for (int ofs = 1; ofs <= 2; ofs <<= 1) {
                cm0 = fmaxf(cm0, __shfl_xor_sync(0xffffffffu, cm0, ofs));
                cm1 = fmaxf(cm1, __shfl_xor_sync(0xffffffffu, cm1, ofs));
            }
            float nm0 = fmaxf(mx0, cm0), nm1 = fmaxf(mx1, cm1);
            float al0 = __expf(mx0 - nm0), al1 = __expf(mx1 - nm1);
            mx0 = nm0; mx1 = nm1;
#pragma unroll
            for (int nf = 0; nf < 4; nf++) {
                o[nf][0] *= al0; o[nf][1] *= al0;
                o[nf][2] *= al1; o[nf][3] *= al1;
            }
#pragma unroll
            for (int nt = 0; nt < 2; nt++) {
                s[nt][0] = __expf(s[nt][0] - nm0);
                s[nt][1] = __expf(s[nt][1] - nm0);
                s[nt][2] = __expf(s[nt][2] - nm1);
                s[nt][3] = __expf(s[nt][3] - nm1);
            }
            float ps0 = s[0][0] + s[0][1] + s[1][0] + s[1][1];
            float ps1 = s[0][2] + s[0][3] + s[1][2] + s[1][3];
#pragma unroll
            for (int ofs = 1; ofs <= 2; ofs <<= 1) {
                ps0 += __shfl_xor_sync(0xffffffffu, ps0, ofs);
                ps1 += __shfl_xor_sync(0xffffffffu, ps1, ofs);
            }
            l0 = l0 * al0 + ps0;
            l1 = l1 * al1 + ps1;

            // P fragment (C->A register reuse)
            unsigned pa[4];
            __half2 p0 = __floats2half2_rn(s[0][0], s[0][1]);
            __half2 p1 = __floats2half2_rn(s[0][2], s[0][3]);
            __half2 p2 = __floats2half2_rn(s[1][0], s[1][1]);
            __half2 p3 = __floats2half2_rn(s[1][2], s[1][3]);
            pa[0] = *(unsigned*)&p0; pa[1] = *(unsigned*)&p1;
            pa[2] = *(unsigned*)&p2; pa[3] = *(unsigned*)&p3;

            // O += P V
            unsigned vf0[4], vf1[4];
            unsigned vAddr = smb + (2 * PADN * 40 + (n0 + vRow) * 40 + vCol) * 2;
            ldsm_x4_t(vf0, vAddr);
            ldsm_x4_t(vf1, vAddr + 32);
            mma16816(o[0], pa, vf0[0], vf0[1]);
            mma16816(o[1], pa, vf0[2], vf0[3]);
            mma16816(o[2], pa, vf1[0], vf1[1]);
            mma16816(o[3], pa, vf1[2], vf1[3]);
        }

        float inv0 = 1.f / l0, inv1 = 1.f / l1;
        int cbase = h * HD + (lane & 3) * 2;
        if (r0g < NTOK) {
            __half* dst = attout + (size_t)(w * NTOK + r0g) * DIM + cbase;
#pragma unroll
            for (int nf = 0; nf < 4; nf++)
                *(__half2*)(dst + nf * 8) = __floats2half2_rn(o[nf][0] * inv0, o[nf][1] * inv0);
        }
        if (r1g < NTOK) {
            __half* dst = attout + (size_t)(w * NTOK + r1g) * DIM + cbase;
#pragma unroll
            for (int nf = 0; nf < 4; nf++)
                *(__half2*)(dst + nf * 8) = __floats2half2_rn(o[nf][2] * inv1, o[nf][3] * inv1);
        }
    }
}

// -------- launch --------
extern "C" void kernel_launch(void* const* d_in, const int* in_sizes, int n_in,
                              void* d_out, int out_size) {
    const float* x     = (const float*)d_in[0];
    const float* n1g   = (const float*)d_in[1];
    const float* n1b   = (const float*)d_in[2];
    const float* qkvw  = (const float*)d_in[3];
    const float* qkvb  = (const float*)d_in[4];
    const float* rel   = (const float*)d_in[5];
    const float* projw = (const float*)d_in[6];
    const float* projb = (const float*)d_in[7];
    const float* n2g   = (const float*)d_in[8];
    const float* n2b   = (const float*)d_in[9];
    const float* fc1w  = (const float*)d_in[10];
    const float* fc1b  = (const float*)d_in[11];
    const float* fc2w  = (const float*)d_in[12];
    const float* fc2b  = (const float*)d_in[13];
    float* out = (float*)d_out;

    __half *xw, *qkvp, *att, *xn2, *hbuf, *wh, *btab;
    float *x1;
    cudaGetSymbolAddress((void**)&xw,   g_xw);
    cudaGetSymbolAddress((void**)&qkvp, g_qkv);
    cudaGetSymbolAddress((void**)&att,  g_att);
    cudaGetSymbolAddress((void**)&x1,   g_x1);
    cudaGetSymbolAddress((void**)&xn2,  g_xn2);
    cudaGetSymbolAddress((void**)&hbuf, g_h);
    cudaGetSymbolAddress((void**)&wh,   g_wh);
    cudaGetSymbolAddress((void**)&btab, g_btab);

    cudaFuncSetAttribute(attn_kernel, cudaFuncAttributeMaxDynamicSharedMemorySize, ATTN_SMEM);
    cudaFuncSetAttribute(mma_gemm<0, __half>, cudaFuncAttributeMaxDynamicSharedMemorySize, GEMM_SMEM);
    cudaFuncSetAttribute(mma_gemm<1, __half>, cudaFuncAttributeMaxDynamicSharedMemorySize, GEMM_SMEM);
    cudaFuncSetAttribute(mma_gemm<2, float>,  cudaFuncAttributeMaxDynamicSharedMemorySize, GEMM_SMEM);
    cudaFuncSetAttribute(mma_gemm<3, float>,  cudaFuncAttributeMaxDynamicSharedMemorySize, GEMM_SMEM);

    // prologues
    wconv_kernel<<<768, 256>>>(qkvw, projw, fc1w, fc2w, wh);
    btab_kernel<<<(8 * NH * PADN * PADN + 255) / 256, 256>>>(rel, btab);
    // 1) LN1 + shift + window partition
    ln_kernel<<<NROWS / 8, 256>>>(x, n1g, n1b, xw, 1);
    // 2) QKV GEMM
    mma_gemm<0, __half><<<dim3(3, NROWS / 128), 256, GEMM_SMEM>>>(xw, wh, qkvb, nullptr, qkvp, NROWS, 384, 128);
    // 3) attention
    attn_kernel<<<NWIN * NH, 256, ATTN_SMEM>>>(qkvp, btab, att);
    // 4) proj + window-reverse + residual
    mma_gemm<2, float><<<dim3(1, NROWS / 128), 256, GEMM_SMEM>>>(att, wh + 49152, projb, x, x1, NROWS, 128, 128);
    // 5) LN2
    ln_kernel<<<NROWS / 8, 256>>>(x1, n2g, n2b, xn2, 0);
    // 6) fc1 + GELU
    mma_gemm<1, __half><<<dim3(4, NROWS / 128), 256, GEMM_SMEM>>>(xn2, wh + 65536, fc1b, nullptr, hbuf, NROWS, 512, 128);
    // 7) fc2 + residual -> out
    mma_gemm<3, float><<<dim3(1, NROWS / 128), 256, GEMM_SMEM>>>(hbuf, wh + 131072, fc2b, x1, out, NROWS, 128, 512);
}

// round 6
// speedup vs baseline: 5.1954x; 1.0660x over previous
#include <cuda_runtime.h>
#include <cuda_fp16.h>
#include <math.h>

#define DIM   128
#define NH    4
#define HD    32
#define WS    7
#define SS    3
#define ZP    14
#define HP    56
#define WP    56
#define NTOK  343
#define PADN  352
#define NWIN  256
#define NROWS (NWIN * NTOK)   // 87808
#define NMLP  512
#define QK_SCALE 0.17677669529663687f

// -------- scratch (static device globals) --------
__device__ __half g_xw [NROWS * DIM];
__device__ __half g_qkv[NROWS * 3 * DIM];
__device__ __half g_att[NROWS * DIM];
__device__ float  g_x1 [NROWS * DIM];
__device__ __half g_xn2[NROWS * DIM];
__device__ __half g_h  [NROWS * NMLP];
__device__ __half g_wh [196608];                       // fp16 weights: qkv|proj|fc1|fc2
__device__ __half g_btab[8 * NH * PADN * PADN];        // bias+mask table (7.9MB)

__device__ __forceinline__ int nat_row(int r) {
    int w = r / NTOK, t = r - w * NTOK;
    int b = w >> 7, wi = w & 127;
    int wz = wi >> 6, wy = (wi >> 3) & 7, wx = wi & 7;
    int lz = t / 49, rem = t - lz * 49, ly = rem / 7, lx = rem - ly * 7;
    int z = wz * WS + lz + SS; if (z >= ZP) z -= ZP;
    int y = wy * WS + ly + SS; if (y >= HP) y -= HP;
    int x = wx * WS + lx + SS; if (x >= WP) x -= WP;
    return ((b * ZP + z) * HP + y) * WP + x;
}

// -------- prologue: fp32 weights -> fp16 --------
__global__ void wconv_kernel(const float* __restrict__ qkvw, const float* __restrict__ projw,
                             const float* __restrict__ fc1w, const float* __restrict__ fc2w,
                             __half* __restrict__ o) {
    int i = blockIdx.x * 256 + threadIdx.x;
    float v;
    if (i < 49152) v = qkvw[i];
    else if (i < 65536) v = projw[i - 49152];
    else if (i < 131072) v = fc1w[i - 65536];
    else v = fc2w[i - 131072];
    o[i] = __float2half(v);
}

// -------- prologue: bias+mask table per (wtype, head) --------
__global__ void btab_kernel(const float* __restrict__ rel, __half* __restrict__ tab) {
    int idx = blockIdx.x * 256 + threadIdx.x;
    if (idx >= 8 * NH * PADN * PADN) return;
    int j = idx % PADN, t1 = idx / PADN;
    int i = t1 % PADN, t2 = t1 / PADN;
    int h = t2 & 3, wt = t2 >> 2;
    float val;
    if (i >= NTOK || j >= NTOK) val = -30000.f;
    else {
        int iz = i / 49, ir = i - iz * 49, iy = ir / 7, ix = ir - iy * 7;
        int jz = j / 49, jr = j - jz * 49, jy = jr / 7, jx = jr - jy * 7;
        int ridx = (iz - jz + 6) * 169 + (iy - jy + 6) * 13 + (ix - jx + 6);
        int ri = ((wt & 4) ? ((iz < 4) ? 1 : 2) : 0) * 9
               + ((wt & 2) ? ((iy < 4) ? 1 : 2) : 0) * 3
               + ((wt & 1) ? ((ix < 4) ? 1 : 2) : 0);
        int rj = ((wt & 4) ? ((jz < 4) ? 1 : 2) : 0) * 9
               + ((wt & 2) ? ((jy < 4) ? 1 : 2) : 0) * 3
               + ((wt & 1) ? ((jx < 4) ? 1 : 2) : 0);
        val = rel[ridx * NH + h] + ((ri == rj) ? 0.f : -100.f);
    }
    tab[idx] = __float2half(val);
}

// -------- LayerNorm: one warp per token, fp16 out (LN1 only) --------
__global__ void ln_kernel(const float* __restrict__ src, const float* __restrict__ g,
                          const float* __restrict__ b, __half* __restrict__ dst, int gather) {
    int token = blockIdx.x * 8 + (threadIdx.x >> 5);
    int lane  = threadIdx.x & 31;
    int srow  = gather ? nat_row(token) : token;
    float4 v = ((const float4*)(src + (size_t)srow * DIM))[lane];
    float s  = v.x + v.y + v.z + v.w;
    float ss = v.x * v.x + v.y * v.y + v.z * v.z + v.w * v.w;
#pragma unroll
    for (int o = 16; o; o >>= 1) {
        s  += __shfl_xor_sync(0xffffffffu, s,  o);
        ss += __shfl_xor_sync(0xffffffffu, ss, o);
    }
    float mean = s * (1.f / 128.f);
    float inv  = rsqrtf(ss * (1.f / 128.f) - mean * mean + 1e-5f);
    float4 gg = ((const float4*)g)[lane];
    float4 bb = ((const float4*)b)[lane];
    __half2 h01 = __floats2half2_rn((v.x - mean) * inv * gg.x + bb.x,
                                    (v.y - mean) * inv * gg.y + bb.y);
    __half2 h23 = __floats2half2_rn((v.z - mean) * inv * gg.z + bb.z,
                                    (v.w - mean) * inv * gg.w + bb.w);
    __half2* d = (__half2*)(dst + (size_t)token * DIM);
    d[lane * 2] = h01; d[lane * 2 + 1] = h23;
}

// ================= MMA helpers =================
__device__ __forceinline__ void ldsm_x4(unsigned (&r)[4], unsigned addr) {
    asm volatile("ldmatrix.sync.aligned.m8n8.x4.shared.b16 {%0,%1,%2,%3}, [%4];"
                 : "=r"(r[0]), "=r"(r[1]), "=r"(r[2]), "=r"(r[3]) : "r"(addr));
}
__device__ __forceinline__ void ldsm_x4_t(unsigned (&r)[4], unsigned addr) {
    asm volatile("ldmatrix.sync.aligned.m8n8.x4.trans.shared.b16 {%0,%1,%2,%3}, [%4];"
                 : "=r"(r[0]), "=r"(r[1]), "=r"(r[2]), "=r"(r[3]) : "r"(addr));
}
__device__ __forceinline__ void mma16816(float (&c)[4], const unsigned (&a)[4],
                                         unsigned b0, unsigned b1) {
    asm volatile("mma.sync.aligned.m16n8k16.row.col.f32.f16.f16.f32 "
                 "{%0,%1,%2,%3},{%4,%5,%6,%7},{%8,%9},{%0,%1,%2,%3};"
                 : "+f"(c[0]), "+f"(c[1]), "+f"(c[2]), "+f"(c[3])
                 : "r"(a[0]), "r"(a[1]), "r"(a[2]), "r"(a[3]), "r"(b0), "r"(b1));
}
__device__ __forceinline__ void cpa16(unsigned dst, const void* src) {
    asm volatile("cp.async.cg.shared.global [%0], [%1], 16;" :: "r"(dst), "l"(src));
}
__device__ __forceinline__ void cpa_commit() { asm volatile("cp.async.commit_group;"); }
template <int N> __device__ __forceinline__ void cpa_wait() {
    asm volatile("cp.async.wait_group %0;" :: "n"(N));
}

// ================= tensor-core GEMM, cp.async 4-stage, 1 sync/iter =============
// BM=128, BN=128, BK=32, 256 thr, warp tile 64x32. A,B fp16 in gmem.
// EPI 0: +bias                       (qkv)
// EPI 1: +bias, GELU, write half     (fc1)
// EPI 2: +bias, scatter nat_row, +res, fused LN2 -> C(x1 float) + C2(xn2 half)
// EPI 3: +bias, +res[r]              (fc2 + residual-2)
#define BK 32
#define STG_A (128 * 40)            // halfs
#define STG_B (BK * 136)
#define STG_TOT (STG_A + STG_B)
#define GEMM_SMEM (4 * STG_TOT * 2) // 75,776 bytes

template <int EPI, typename CT>
__global__ void __launch_bounds__(256, 2) mma_gemm(
        const __half* __restrict__ A, const __half* __restrict__ B,
        const float* __restrict__ bias, const float* __restrict__ res,
        CT* __restrict__ C, const float* __restrict__ g2,
        const float* __restrict__ b2, __half* __restrict__ C2,
        int M, int N, int K) {
    extern __shared__ __half gsm[];
    const int tid  = threadIdx.x;
    const int lane = tid & 31, warp = tid >> 5;
    const int mw = warp >> 2, nw = warp & 3;
    const int bm = blockIdx.y * 128, bn = blockIdx.x * 128;

    const int arow = tid >> 1, ac0 = (tid & 1) * 16;
    const int brow = tid >> 3, bc0 = (tid & 7) * 16;
    const unsigned smbase = (unsigned)__cvta_generic_to_shared(gsm);

    float acc[4][4][4];
#pragma unroll
    for (int i = 0; i < 4; i++)
#pragma unroll
        for (int j = 0; j < 4; j++)
#pragma unroll
            for (int l = 0; l < 4; l++) acc[i][j][l] = 0.f;

    const int niter = K / BK;
    auto issue = [&](int it) {
        int s = it & 3;
        unsigned da = smbase + (s * STG_TOT + arow * 40 + ac0) * 2;
        const __half* pa = A + (size_t)(bm + arow) * K + it * BK + ac0;
        cpa16(da, pa); cpa16(da + 16, pa + 8);
        unsigned db = smbase + (s * STG_TOT + STG_A + brow * 136 + bc0) * 2;
        const __half* pb = B + (size_t)(it * BK + brow) * N + bn + bc0;
        cpa16(db, pb); cpa16(db + 16, pb + 8);
        cpa_commit();
    };
    issue(0);
    if (niter > 1) issue(1);
    if (niter > 2) issue(2);

    const unsigned aLane = ((lane & 15) * 40 + (lane >> 4) * 8) * 2 + (unsigned)(mw * 64 * 40 * 2);
    const unsigned bLane = (((lane & 7) + ((lane >> 3) & 1) * 8) * 136 + (lane >> 4) * 8) * 2
                           + (unsigned)(nw * 32 * 2);

    for (int it = 0; it < niter; it++) {
        // retire exactly group `it` (no empty groups exist)
        if (it + 2 < niter)      cpa_wait<2>();
        else if (it + 1 < niter) cpa_wait<1>();
        else                     cpa_wait<0>();
        __syncthreads();
        if (it + 3 < niter) issue(it + 3);   // overwrites stage (it-1)&3: reads done pre-sync
        int s = it & 3;
        unsigned aBase = smbase + s * STG_TOT * 2 + aLane;
        unsigned bBase = smbase + (s * STG_TOT + STG_A) * 2 + bLane;
#pragma unroll
        for (int ks = 0; ks < 2; ks++) {
            unsigned a[4][4], b[2][4];
#pragma unroll
            for (int mf = 0; mf < 4; mf++) ldsm_x4(a[mf], aBase + mf * (16 * 40 * 2) + ks * 32);
#pragma unroll
            for (int np = 0; np < 2; np++) ldsm_x4_t(b[np], bBase + np * 32 + ks * (16 * 136 * 2));
#pragma unroll
            for (int mf = 0; mf < 4; mf++)
#pragma unroll
                for (int nf = 0; nf < 4; nf++)
                    mma16816(acc[mf][nf], a[mf], b[nf >> 1][(nf & 1) * 2],
                             b[nf >> 1][(nf & 1) * 2 + 1]);
        }
    }

    if constexpr (EPI == 2) {
        // proj + residual + fused LayerNorm2. BN=128 spans the full row.
        float* stat = (float*)gsm;               // [128][8]: sum[0:4), sumsq[4:8)
        int orA[4], orB[4];
        __syncthreads();                          // mainloop smem reads finished everywhere
#pragma unroll
        for (int mf = 0; mf < 4; mf++) {
            int lr = mw * 64 + mf * 16 + (lane >> 2);
            orA[mf] = nat_row(bm + lr);
            orB[mf] = nat_row(bm + lr + 8);
            float s0 = 0.f, q0 = 0.f, s1 = 0.f, q1 = 0.f;
#pragma unroll
            for (int nf = 0; nf < 4; nf++) {
                int c = nw * 32 + nf * 8 + (lane & 3) * 2;
                float bv0 = bias[c], bv1 = bias[c + 1];
                float v00 = acc[mf][nf][0] + bv0 + res[(size_t)orA[mf] * DIM + c];
                float v01 = acc[mf][nf][1] + bv1 + res[(size_t)orA[mf] * DIM + c + 1];
                float v10 = acc[mf][nf][2] + bv0 + res[(size_t)orB[mf] * DIM + c];
                float v11 = acc[mf][nf][3] + bv1 + res[(size_t)orB[mf] * DIM + c + 1];
                acc[mf][nf][0] = v00; acc[mf][nf][1] = v01;
                acc[mf][nf][2] = v10; acc[mf][nf][3] = v11;
                s0 += v00 + v01; q0 += v00 * v00 + v01 * v01;
                s1 += v10 + v11; q1 += v10 * v10 + v11 * v11;
            }
#pragma unroll
            for (int ofs = 1; ofs <= 2; ofs <<= 1) {
                s0 += __shfl_xor_sync(0xffffffffu, s0, ofs);
                q0 += __shfl_xor_sync(0xffffffffu, q0, ofs);
                s1 += __shfl_xor_sync(0xffffffffu, s1, ofs);
                q1 += __shfl_xor_sync(0xffffffffu, q1, ofs);
            }
            if ((lane & 3) == 0) {
                stat[lr * 8 + nw] = s0;          stat[lr * 8 + nw + 4] = q0;
                stat[(lr + 8) * 8 + nw] = s1;    stat[(lr + 8) * 8 + nw + 4] = q1;
            }
        }
        __syncthreads();
#pragma unroll
        for (int mf = 0; mf < 4; mf++) {
            int lr = mw * 64 + mf * 16 + (lane >> 2);
            float s0 = stat[lr * 8] + stat[lr * 8 + 1] + stat[lr * 8 + 2] + stat[lr * 8 + 3];
            float q0 = stat[lr * 8 + 4] + stat[lr * 8 + 5] + stat[lr * 8 + 6] + stat[lr * 8 + 7];
            float s1 = stat[(lr + 8) * 8]     + stat[(lr + 8) * 8 + 1]
                     + stat[(lr + 8) * 8 + 2] + stat[(lr + 8) * 8 + 3];
            float q1 = stat[(lr + 8) * 8 + 4] + stat[(lr + 8) * 8 + 5]
                     + stat[(lr + 8) * 8 + 6] + stat[(lr + 8) * 8 + 7];
            float m0 = s0 * (1.f / 128.f);
            float i0 = rsqrtf(q0 * (1.f / 128.f) - m0 * m0 + 1e-5f);
            float m1 = s1 * (1.f / 128.f);
            float i1 = rsqrtf(q1 * (1.f / 128.f) - m1 * m1 + 1e-5f);
#pragma unroll
            for (int nf = 0; nf < 4; nf++) {
                int c = nw * 32 + nf * 8 + (lane & 3) * 2;
                float g0 = g2[c], g1 = g2[c + 1], bb0 = b2[c], bb1 = b2[c + 1];
                float v00 = acc[mf][nf][0], v01 = acc[mf][nf][1];
                float v10 = acc[mf][nf][2], v11 = acc[mf][nf][3];
                *(float2*)((float*)C + (size_t)orA[mf] * DIM + c) = make_float2(v00, v01);
                *(float2*)((float*)C + (size_t)orB[mf] * DIM + c) = make_float2(v10, v11);
                *(__half2*)(C2 + (size_t)orA[mf] * DIM + c) =
                    __floats2half2_rn((v00 - m0) * i0 * g0 + bb0, (v01 - m0) * i0 * g1 + bb1);
                *(__half2*)(C2 + (size_t)orB[mf] * DIM + c) =
                    __floats2half2_rn((v10 - m1) * i1 * g0 + bb0, (v11 - m1) * i1 * g1 + bb1);
            }
        }
    } else {
#pragma unroll
        for (int mf = 0; mf < 4; mf++) {
            int r0 = bm + mw * 64 + mf * 16 + (lane >> 2);
            int r1 = r0 + 8;
#pragma unroll
            for (int nf = 0; nf < 4; nf++) {
                int c = bn + nw * 32 + nf * 8 + (lane & 3) * 2;
                float bv0 = bias[c], bv1 = bias[c + 1];
                float v00 = acc[mf][nf][0] + bv0, v01 = acc[mf][nf][1] + bv1;
                float v10 = acc[mf][nf][2] + bv0, v11 = acc[mf][nf][3] + bv1;
                if (EPI == 1) {
                    v00 = 0.5f * v00 * (1.f + erff(v00 * 0.7071067811865475f));
                    v01 = 0.5f * v01 * (1.f + erff(v01 * 0.7071067811865475f));
                    v10 = 0.5f * v10 * (1.f + erff(v10 * 0.7071067811865475f));
                    v11 = 0.5f * v11 * (1.f + erff(v11 * 0.7071067811865475f));
                }
                if (EPI == 3) {
                    v00 += res[(size_t)r0 * DIM + c];    v01 += res[(size_t)r0 * DIM + c + 1];
                    v10 += res[(size_t)r1 * DIM + c];    v11 += res[(size_t)r1 * DIM + c + 1];
                }
                if constexpr (sizeof(CT) == 2) {
                    *(__half2*)((__half*)C + (size_t)r0 * N + c) = __floats2half2_rn(v00, v01);
                    *(__half2*)((__half*)C + (size_t)r1 * N + c) = __floats2half2_rn(v10, v11);
                } else {
                    *(float2*)((float*)C + (size_t)r0 * N + c) = make_float2(v00, v01);
                    *(float2*)((float*)C + (size_t)r1 * N + c) = make_float2(v10, v11);
                }
            }
        }
    }
}

// ================= FA2-style windowed attention (fp16 mma) =================
// CTA = (window, head), 352 threads = 11 warps x exactly 2 query tiles.
// smem: Q,K,V [352][40] halfs = 84,480 B. 2 CTAs/SM.
#define ATTN_SMEM (3 * PADN * 40 * 2)

__global__ void __launch_bounds__(352, 2) attn_kernel(
        const __half* __restrict__ qkv, const __half* __restrict__ tab,
        __half* __restrict__ attout) {
    extern __shared__ __half asm_[];
    __half* sQ = asm_;
    __half* sK = asm_ + PADN * 40;
    __half* sV = asm_ + 2 * PADN * 40;

    const int w = blockIdx.x >> 2, h = blockIdx.x & 3;
    const int tid = threadIdx.x, lane = tid & 31, warp = tid >> 5;

    // stage Q,K,V (half, 16B chunks); zero pad rows. 1408 = 4*352.
    for (int idx = tid; idx < PADN * 4; idx += 352) {
        int t = idx >> 2, c = (idx & 3) * 8;
        uint4 zq = {0,0,0,0}, zk = zq, zv = zq;
        if (t < NTOK) {
            const __half* base = qkv + (size_t)(w * NTOK + t) * (3 * DIM) + h * HD + c;
            zq = *(const uint4*)base;
            zk = *(const uint4*)(base + DIM);
            zv = *(const uint4*)(base + 2 * DIM);
        }
        *(uint4*)&sQ[t * 40 + c] = zq;
        *(uint4*)&sK[t * 40 + c] = zk;
        *(uint4*)&sV[t * 40 + c] = zv;
    }
    __syncthreads();

    const int wi = w & 127;
    const int wt = (((wi >> 6) & 1) << 2) | ((((wi >> 3) & 7) == 7) ? 2 : 0) | (((wi & 7) == 7) ? 1 : 0);
    const __half* tb = tab + (size_t)(wt * NH + h) * PADN * PADN;
    const unsigned smb = (unsigned)__cvta_generic_to_shared(asm_);
    const unsigned kvRow = (unsigned)((lane & 7) + ((lane >> 4) & 1) * 8);
    const unsigned kvCol = (unsigned)(((lane >> 3) & 1) * 8);
    const unsigned vRow  = (unsigned)((lane & 7) + ((lane >> 3) & 1) * 8);
    const unsigned vCol  = (unsigned)((lane >> 4) * 8);

    for (int mt = warp; mt < 22; mt += 11) {
        const int m0 = mt * 16;
        unsigned aq[2][4];
        {
            unsigned aAddr = smb + ((m0 + (lane & 15)) * 40 + (lane >> 4) * 8) * 2;
            ldsm_x4(aq[0], aAddr);
            ldsm_x4(aq[1], aAddr + 32);
        }
        const int r0g = m0 + (lane >> 2), r1g = r0g + 8;
        const __half* tr0 = tb + (size_t)r0g * PADN;
        const __half* tr1 = tb + (size_t)r1g * PADN;

        float o[4][4];
#pragma unroll
        for (int i = 0; i < 4; i++)
#pragma unroll
            for (int j = 0; j < 4; j++) o[i][j] = 0.f;
        float mx0 = -1e30f, mx1 = -1e30f, l0 = 0.f, l1 = 0.f;

        for (int n0 = 0; n0 < PADN; n0 += 16) {
            // S = Q K^T (two 16x8 tiles)
            float s[2][4] = {{0,0,0,0},{0,0,0,0}};
            unsigned kf0[4], kf1[4];
            unsigned kAddr = smb + (PADN * 40 + (n0 + kvRow) * 40 + kvCol) * 2;
            ldsm_x4(kf0, kAddr);           // k 0..15
            ldsm_x4(kf1, kAddr + 32);      // k 16..31
            mma16816(s[0], aq[0], kf0[0], kf0[1]);
            mma16816(s[0], aq[1], kf1[0], kf1[1]);
            mma16816(s[1], aq[0], kf0[2], kf0[3]);
            mma16816(s[1], aq[1], kf1[2], kf1[3]);

            // bias+mask (+ fold QK scale)
            int jc = n0 + (lane & 3) * 2;
#pragma unroll
            for (int nt = 0; nt < 2; nt++) {
                float2 b0 = __half22float2(*(const __half2*)(tr0 + jc + nt * 8));
                float2 b1 = __half22float2(*(const __half2*)(tr1 + jc + nt * 8));
                s[nt][0] = s[nt][0] * QK_SCALE + b0.x;
                s[nt][1] = s[nt][1] * QK_SCALE + b0.y;
                s[nt][2] = s[nt][2] * QK_SCALE + b1.x;
                s[nt][3] = s[nt][3] * QK_SCALE + b1.y;
            }

            // online softmax
            float cm0 = fmaxf(fmaxf(s[0][0], s[0][1]), fmaxf(s[1][0], s[1][1]));
            float cm1 = fmaxf(fmaxf(s[0][2], s[0][3]), fmaxf(s[1][2], s[1][3]));
#pragma unroll
            for (int ofs = 1; ofs <= 2; ofs <<= 1) {
                cm0 = fmaxf(cm0, __shfl_xor_sync(0xffffffffu, cm0, ofs));
                cm1 = fmaxf(cm1, __shfl_xor_sync(0xffffffffu, cm1, ofs));
            }
            float nm0 = fmaxf(mx0, cm0), nm1 = fmaxf(mx1, cm1);
            float al0 = __expf(mx0 - nm0), al1 = __expf(mx1 - nm1);
            mx0 = nm0; mx1 = nm1;
#pragma unroll
            for (int nf = 0; nf < 4; nf++) {
                o[nf][0] *= al0; o[nf][1] *= al0;
                o[nf][2] *= al1; o[nf][3] *= al1;
            }
#pragma unroll
            for (int nt = 0; nt < 2; nt++) {
                s[nt][0] = __expf(s[nt][0] - nm0);
                s[nt][1] = __expf(s[nt][1] - nm0);
                s[nt][2] = __expf(s[nt][2] - nm1);
                s[nt][3] = __expf(s[nt][3] - nm1);
            }
            float ps0 = s[0][0] + s[0][1] + s[1][0] + s[1][1];
            float ps1 = s[0][2] + s[0][3] + s[1][2] + s[1][3];
#pragma unroll
            for (int ofs = 1; ofs <= 2; ofs <<= 1) {
                ps0 += __shfl_xor_sync(0xffffffffu, ps0, ofs);
                ps1 += __shfl_xor_sync(0xffffffffu, ps1, ofs);
            }
            l0 = l0 * al0 + ps0;
            l1 = l1 * al1 + ps1;

            // P fragment (C->A register reuse)
            unsigned pa[4];
            __half2 p0 = __floats2half2_rn(s[0][0], s[0][1]);
            __half2 p1 = __floats2half2_rn(s[0][2], s[0][3]);
            __half2 p2 = __floats2half2_rn(s[1][0], s[1][1]);
            __half2 p3 = __floats2half2_rn(s[1][2], s[1][3]);
            pa[0] = *(unsigned*)&p0; pa[1] = *(unsigned*)&p1;
            pa[2] = *(unsigned*)&p2; pa[3] = *(unsigned*)&p3;

            // O += P V
            unsigned vf0[4], vf1[4];
            unsigned vAddr = smb + (2 * PADN * 40 + (n0 + vRow) * 40 + vCol) * 2;
            ldsm_x4_t(vf0, vAddr);
            ldsm_x4_t(vf1, vAddr + 32);
            mma16816(o[0], pa, vf0[0], vf0[1]);
            mma16816(o[1], pa, vf0[2], vf0[3]);
            mma16816(o[2], pa, vf1[0], vf1[1]);
            mma16816(o[3], pa, vf1[2], vf1[3]);
        }

        float inv0 = 1.f / l0, inv1 = 1.f / l1;
        int cbase = h * HD + (lane & 3) * 2;
        if (r0g < NTOK) {
            __half* dst = attout + (size_t)(w * NTOK + r0g) * DIM + cbase;
#pragma unroll
            for (int nf = 0; nf < 4; nf++)
                *(__half2*)(dst + nf * 8) = __floats2half2_rn(o[nf][0] * inv0, o[nf][1] * inv0);
        }
        if (r1g < NTOK) {
            __half* dst = attout + (size_t)(w * NTOK + r1g) * DIM + cbase;
#pragma unroll
            for (int nf = 0; nf < 4; nf++)
                *(__half2*)(dst + nf * 8) = __floats2half2_rn(o[nf][2] * inv1, o[nf][3] * inv1);
        }
    }
}

// -------- launch --------
extern "C" void kernel_launch(void* const* d_in, const int* in_sizes, int n_in,
                              void* d_out, int out_size) {
    const float* x     = (const float*)d_in[0];
    const float* n1g   = (const float*)d_in[1];
    const float* n1b   = (const float*)d_in[2];
    const float* qkvw  = (const float*)d_in[3];
    const float* qkvb  = (const float*)d_in[4];
    const float* rel   = (const float*)d_in[5];
    const float* projw = (const float*)d_in[6];
    const float* projb = (const float*)d_in[7];
    const float* n2g   = (const float*)d_in[8];
    const float* n2b   = (const float*)d_in[9];
    const float* fc1w  = (const float*)d_in[10];
    const float* fc1b  = (const float*)d_in[11];
    const float* fc2w  = (const float*)d_in[12];
    const float* fc2b  = (const float*)d_in[13];
    float* out = (float*)d_out;

    __half *xw, *qkvp, *att, *xn2, *hbuf, *wh, *btab;
    float *x1;
    cudaGetSymbolAddress((void**)&xw,   g_xw);
    cudaGetSymbolAddress((void**)&qkvp, g_qkv);
    cudaGetSymbolAddress((void**)&att,  g_att);
    cudaGetSymbolAddress((void**)&x1,   g_x1);
    cudaGetSymbolAddress((void**)&xn2,  g_xn2);
    cudaGetSymbolAddress((void**)&hbuf, g_h);
    cudaGetSymbolAddress((void**)&wh,   g_wh);
    cudaGetSymbolAddress((void**)&btab, g_btab);

    cudaFuncSetAttribute(attn_kernel, cudaFuncAttributeMaxDynamicSharedMemorySize, ATTN_SMEM);
    cudaFuncSetAttribute(mma_gemm<0, __half>, cudaFuncAttributeMaxDynamicSharedMemorySize, GEMM_SMEM);
    cudaFuncSetAttribute(mma_gemm<1, __half>, cudaFuncAttributeMaxDynamicSharedMemorySize, GEMM_SMEM);
    cudaFuncSetAttribute(mma_gemm<2, float>,  cudaFuncAttributeMaxDynamicSharedMemorySize, GEMM_SMEM);
    cudaFuncSetAttribute(mma_gemm<3, float>,  cudaFuncAttributeMaxDynamicSharedMemorySize, GEMM_SMEM);

    // prologues
    wconv_kernel<<<768, 256>>>(qkvw, projw, fc1w, fc2w, wh);
    btab_kernel<<<(8 * NH * PADN * PADN + 255) / 256, 256>>>(rel, btab);
    // 1) LN1 + shift + window partition
    ln_kernel<<<NROWS / 8, 256>>>(x, n1g, n1b, xw, 1);
    // 2) QKV GEMM
    mma_gemm<0, __half><<<dim3(3, NROWS / 128), 256, GEMM_SMEM>>>(
        xw, wh, qkvb, nullptr, qkvp, nullptr, nullptr, nullptr, NROWS, 384, 128);
    // 3) attention
    attn_kernel<<<NWIN * NH, 352, ATTN_SMEM>>>(qkvp, btab, att);
    // 4) proj + window-reverse + residual + fused LN2
    mma_gemm<2, float><<<dim3(1, NROWS / 128), 256, GEMM_SMEM>>>(
        att, wh + 49152, projb, x, x1, n2g, n2b, xn2, NROWS, 128, 128);
    // 5) fc1 + GELU
    mma_gemm<1, __half><<<dim3(4, NROWS / 128), 256, GEMM_SMEM>>>(
        xn2, wh + 65536, fc1b, nullptr, hbuf, nullptr, nullptr, nullptr, NROWS, 512, 128);
    // 6) fc2 + residual -> out
    mma_gemm<3, float><<<dim3(1, NROWS / 128), 256, GEMM_SMEM>>>(
        hbuf, wh + 131072, fc2b, x1, out, nullptr, nullptr, nullptr, NROWS, 128, 512);
}